// round 11
// baseline (speedup 1.0000x reference)
#include <cuda_runtime.h>
#include <cuda_fp16.h>
#include <cstdint>

typedef unsigned long long u64;

#define NTOK 8192
#define GCTAS 296
#define NUNITS 8192                      // 64 qtiles * 128 chunks

// ---- smem layout (bytes) ----
#define A_OFF    0                       // 128 rows x 128B phi (pitch 144)
#define B_OFF0   18432
#define B_OFF1   36864                   // psi tiles, 128 rows x 128B (pitch 144)
#define VT_OFF(p) (55296 + (p) * 1152)   // 8 rows x 128B (pitch 144)
#define P_OFF    57600                   // 8 warps x (32 rows x 80B) = 20480
#define RED_OFF  78080                   // 128 x 8 floats
#define SMEM_TOTAL 82176                 // x2 CTAs = 164352 <= 228KB carveout

// ---------------- device scratch ----------------
__device__ __align__(16) __half g_a [NTOK * 64];    // phi_i (real, K=64)
__device__ __align__(16) __half g_b [NTOK * 128];   // rows 2j: Re(psi_j), 2j+1: Im(psi_j)
__device__ __align__(16) __half g_vt[8 * NTOK];     // rows 0-5: <Z_q>, row6: ones, row7: 0
__device__ float  g_part[(size_t)64 * 8 * 128 * 8]; // [qtile][slot(8)][tok][8]
__device__ float2 g_trig[3 * 24];

// ---------------- PTX helpers ----------------
__device__ __forceinline__ uint32_t smem_u32(const void* p) {
    uint32_t a;
    asm("{ .reg .u64 t; cvta.to.shared.u64 t, %1; cvt.u32.u64 %0, t; }" : "=r"(a) : "l"(p));
    return a;
}
__device__ __forceinline__ void cp16(uint32_t s, const void* g) {
    asm volatile("cp.async.cg.shared.global [%0], [%1], 16;" :: "r"(s), "l"(g));
}
__device__ __forceinline__ void cp_commit() { asm volatile("cp.async.commit_group;"); }

__device__ __forceinline__ void ldsm_x4(uint32_t& r0, uint32_t& r1, uint32_t& r2, uint32_t& r3, uint32_t a) {
    asm volatile("ldmatrix.sync.aligned.m8n8.x4.shared.b16 {%0,%1,%2,%3}, [%4];"
                 : "=r"(r0), "=r"(r1), "=r"(r2), "=r"(r3) : "r"(a));
}
__device__ __forceinline__ void ldsm_x2(uint32_t& r0, uint32_t& r1, uint32_t a) {
    asm volatile("ldmatrix.sync.aligned.m8n8.x2.shared.b16 {%0,%1}, [%2];"
                 : "=r"(r0), "=r"(r1) : "r"(a));
}
__device__ __forceinline__ void mma16816(float* c, const uint32_t* a, const uint32_t* b) {
    asm volatile("mma.sync.aligned.m16n8k16.row.col.f32.f16.f16.f32 "
                 "{%0,%1,%2,%3}, {%4,%5,%6,%7}, {%8,%9}, {%0,%1,%2,%3};"
                 : "+f"(c[0]), "+f"(c[1]), "+f"(c[2]), "+f"(c[3])
                 : "r"(a[0]), "r"(a[1]), "r"(a[2]), "r"(a[3]), "r"(b[0]), "r"(b[1]));
}
__device__ __forceinline__ void sts16(uint32_t a, float v) {
    unsigned short u = __half_as_ushort(__float2half_rn(v));
    asm volatile("st.shared.b16 [%0], %1;" :: "r"(a), "h"(u));
}

// ---------------- quantum gates ----------------
__device__ __forceinline__ void ry_sc(float s, float c, int q, int lane,
        float& a0x, float& a0y, float& a1x, float& a1y)
{
    if (q == 5) {
        float n0x = c*a0x - s*a1x, n0y = c*a0y - s*a1y;
        float n1x = s*a0x + c*a1x, n1y = s*a0y + c*a1y;
        a0x = n0x; a0y = n0y; a1x = n1x; a1y = n1y;
    } else {
        int sh = 4 - q, m = 1 << sh;
        float o0x = __shfl_xor_sync(0xffffffffu, a0x, m);
        float o0y = __shfl_xor_sync(0xffffffffu, a0y, m);
        float o1x = __shfl_xor_sync(0xffffffffu, a1x, m);
        float o1y = __shfl_xor_sync(0xffffffffu, a1y, m);
        float sg = ((lane >> sh) & 1) ? s : -s;
        a0x = c*a0x + sg*o0x; a0y = c*a0y + sg*o0y;
        a1x = c*a1x + sg*o1x; a1y = c*a1y + sg*o1y;
    }
}

__device__ __forceinline__ void rz_sc(float s, float c, int q, int lane,
        float& a0x, float& a0y, float& a1x, float& a1y)
{
    if (q == 5) {
        float n0x = a0x*c + a0y*s, n0y = a0y*c - a0x*s;
        float n1x = a1x*c - a1y*s, n1y = a1y*c + a1x*s;
        a0x = n0x; a0y = n0y; a1x = n1x; a1y = n1y;
    } else {
        float t = ((lane >> (4 - q)) & 1) ? s : -s;
        float n0x = a0x*c - a0y*t, n0y = a0y*c + a0x*t;
        float n1x = a1x*c - a1y*t, n1y = a1y*c + a1x*t;
        a0x = n0x; a0y = n0y; a1x = n1x; a1y = n1y;
    }
}

__device__ __forceinline__ void cnot_ll(int csh, int tmask, int lane,
        float& a0x, float& a0y, float& a1x, float& a1y)
{
    float o0x = __shfl_xor_sync(0xffffffffu, a0x, tmask);
    float o0y = __shfl_xor_sync(0xffffffffu, a0y, tmask);
    float o1x = __shfl_xor_sync(0xffffffffu, a1x, tmask);
    float o1y = __shfl_xor_sync(0xffffffffu, a1y, tmask);
    if ((lane >> csh) & 1) { a0x = o0x; a0y = o0y; a1x = o1x; a1y = o1y; }
}

__device__ __forceinline__ void pqc_fwd(const float2* trig, int lane,
        float& a0x, float& a0y, float& a1x, float& a1y)
{
    #pragma unroll
    for (int l = 0; l < 2; l++) {
        #pragma unroll
        for (int q = 0; q < 6; q++) {
            float2 ty = trig[(l * 6 + q) * 2 + 0];
            ry_sc(ty.x, ty.y, q, lane, a0x, a0y, a1x, a1y);
            float2 tz = trig[(l * 6 + q) * 2 + 1];
            rz_sc(tz.x, tz.y, q, lane, a0x, a0y, a1x, a1y);
        }
        cnot_ll(4, 8, lane, a0x, a0y, a1x, a1y);
        cnot_ll(3, 4, lane, a0x, a0y, a1x, a1y);
        cnot_ll(2, 2, lane, a0x, a0y, a1x, a1y);
        cnot_ll(1, 1, lane, a0x, a0y, a1x, a1y);
        if (lane & 1) {
            float t;
            t = a0x; a0x = a1x; a1x = t;
            t = a0y; a0y = a1y; a1y = t;
        }
        a1x = __shfl_xor_sync(0xffffffffu, a1x, 16);
        a1y = __shfl_xor_sync(0xffffffffu, a1y, 16);
    }
}

__device__ __forceinline__ void pqc_inv(const float2* trig, int lane,
        float& a0x, float& a0y, float& a1x, float& a1y)
{
    #pragma unroll
    for (int l = 1; l >= 0; l--) {
        a1x = __shfl_xor_sync(0xffffffffu, a1x, 16);
        a1y = __shfl_xor_sync(0xffffffffu, a1y, 16);
        if (lane & 1) {
            float t;
            t = a0x; a0x = a1x; a1x = t;
            t = a0y; a0y = a1y; a1y = t;
        }
        cnot_ll(1, 1, lane, a0x, a0y, a1x, a1y);
        cnot_ll(2, 2, lane, a0x, a0y, a1x, a1y);
        cnot_ll(3, 4, lane, a0x, a0y, a1x, a1y);
        cnot_ll(4, 8, lane, a0x, a0y, a1x, a1y);
        #pragma unroll
        for (int q = 0; q < 6; q++) {
            float2 tz = trig[(l * 6 + q) * 2 + 1];
            rz_sc(-tz.x, tz.y, q, lane, a0x, a0y, a1x, a1y);
            float2 ty = trig[(l * 6 + q) * 2 + 0];
            ry_sc(-ty.x, ty.y, q, lane, a0x, a0y, a1x, a1y);
        }
    }
}

__global__ void trig_kernel(const float* __restrict__ pq,
                            const float* __restrict__ pk,
                            const float* __restrict__ pv)
{
    int i = threadIdx.x;
    if (i < 72) {
        int set = i / 24, r = i % 24;
        const float* p = (set == 0) ? pq : (set == 1) ? pk : pv;
        float s, c;
        sincosf(0.5f * p[r], &s, &c);
        g_trig[i] = make_float2(s, c);
    }
}

__global__ void prep_kernel(const float* __restrict__ x)
{
    int gw   = (blockIdx.x * blockDim.x + threadIdx.x) >> 5;
    int lane = threadIdx.x & 31;
    int set  = gw >> 13;            // 0=Q(phi), 1=K(psi), 2=V
    int tok  = gw & (NTOK - 1);

    float a0x = (lane == 0) ? 1.f : 0.f, a0y = 0.f, a1x = 0.f, a1y = 0.f;

    #pragma unroll
    for (int q = 0; q < 6; q++) {
        float s, c;
        sincosf(0.5f * x[tok * 6 + q], &s, &c);
        ry_sc(s, c, q, lane, a0x, a0y, a1x, a1y);
    }

    if (set == 0) {
        ((__half2*)g_a)[tok * 32 + lane] = __floats2half2_rn(a0x, a1x);
    } else if (set == 1) {
        pqc_fwd(g_trig + 24, lane, a0x, a0y, a1x, a1y);   // K-PQC
        pqc_inv(g_trig + 0,  lane, a0x, a0y, a1x, a1y);   // inverse Q-PQC
        ((__half2*)g_b)[(tok * 2 + 0) * 32 + lane] = __floats2half2_rn(a0x, a1x);
        ((__half2*)g_b)[(tok * 2 + 1) * 32 + lane] = __floats2half2_rn(a0y, a1y);
    } else {
        pqc_fwd(g_trig + 48, lane, a0x, a0y, a1x, a1y);   // V-PQC
        float p0 = a0x*a0x + a0y*a0y;
        float p1 = a1x*a1x + a1y*a1y;
        int d0 = lane * 2, d1 = lane * 2 + 1;
        #pragma unroll
        for (int q = 0; q < 6; q++) {
            float s0 = ((d0 >> (5 - q)) & 1) ? -1.f : 1.f;
            float s1 = ((d1 >> (5 - q)) & 1) ? -1.f : 1.f;
            float z = s0 * p0 + s1 * p1;
            #pragma unroll
            for (int o = 16; o; o >>= 1) z += __shfl_xor_sync(0xffffffffu, z, o);
            if (lane == 0) g_vt[q * NTOK + tok] = __float2half_rn(z);
        }
        if (lane == 0) {
            g_vt[6 * NTOK + tok] = __float2half_rn(1.f);   // ones row -> den
            g_vt[7 * NTOK + tok] = __float2half_rn(0.f);
        }
    }
}

// ---------------- fused attention ----------------
extern __shared__ char smx[];

// one 64-key chunk: 128 psi col-rows (16KB) + Vt 8 rows x 128B (1KB)
__device__ __forceinline__ void issue_chunk(uint32_t smb, uint32_t boff, uint32_t vtoff,
                                            int kb, int tid)
{
    #pragma unroll
    for (int it = 0; it < 5; it++) {
        int i = it * 256 + tid;
        if (i < 1024) {
            int row = i >> 3, ch = i & 7;
            cp16(smb + boff + row * 144 + ch * 16,
                 g_b + (size_t)(kb * 2 + row) * 64 + ch * 8);
        } else if (i < 1088) {
            int j = i - 1024, row = j >> 3, ch = j & 7;
            cp16(smb + vtoff + row * 144 + ch * 16,
                 g_vt + (size_t)row * NTOK + kb + ch * 8);
        }
    }
    cp_commit();
}

__device__ __forceinline__ void flush_O(char* sm, float O[2][4], int b, int q,
                                        int mwarp, int wcol, int lane, int tid)
{
    float2* red = (float2*)(sm + RED_OFF);
    __syncthreads();
    int r0 = mwarp + (lane >> 2);
    int cc = lane & 3;
    if (wcol == 0) {
        #pragma unroll
        for (int rt = 0; rt < 2; rt++) {
            red[(r0 + rt * 16) * 4 + cc]     = make_float2(O[rt][0], O[rt][1]);
            red[(r0 + rt * 16 + 8) * 4 + cc] = make_float2(O[rt][2], O[rt][3]);
        }
    }
    __syncthreads();
    if (wcol == 1) {
        #pragma unroll
        for (int rt = 0; rt < 2; rt++) {
            float2 v0 = red[(r0 + rt * 16) * 4 + cc];
            v0.x += O[rt][0]; v0.y += O[rt][1];
            red[(r0 + rt * 16) * 4 + cc] = v0;
            float2 v1 = red[(r0 + rt * 16 + 8) * 4 + cc];
            v1.x += O[rt][2]; v1.y += O[rt][3];
            red[(r0 + rt * 16 + 8) * 4 + cc] = v1;
        }
    }
    __syncthreads();
    if (tid < 128) {
        int slot = b - ((q * 128 + 1) * GCTAS - 1) / NUNITS;
        const float4* src = (const float4*)((const float*)(sm + RED_OFF) + tid * 8);
        float4* dst = (float4*)(g_part + ((size_t)(q * 8 + slot) * 128 + tid) * 8);
        dst[0] = src[0]; dst[1] = src[1];
    }
}

__global__ void __launch_bounds__(256, 2) attn_kernel()
{
    char* sm = smx;
    uint32_t smb = smem_u32(sm);
    int tid  = threadIdx.x;
    int wid  = tid >> 5, lane = tid & 31;
    int wrow = wid & 3, wcol = wid >> 2;      // warp grid 4x2
    int mwarp = wrow * 32;
    int b = blockIdx.x;
    int u0 = ((long long)NUNITS * b) / GCTAS;
    int u1 = ((long long)NUNITS * (b + 1)) / GCTAS;

    uint32_t pbase = smb + P_OFF + wid * 2560;

    // prologue: prefetch chunk u0 into its parity buffer
    {
        int p0 = u0 & 1;
        issue_chunk(smb, p0 ? B_OFF1 : B_OFF0, VT_OFF(p0), 64 * (u0 & 127), tid);
    }

    uint32_t afr[2][4][4];
    float O[2][4];
    int qcur = -1;
    int brow_l = wcol * 64 + (lane >> 4) * 8 + (lane & 7);
    int boffk  = ((lane >> 3) & 1) * 16;
    int l4 = lane & 15;

    for (int u = u0; u < u1; u++) {
        int q = u >> 7, p = u & 1;
        bool newq = (q != qcur);
        bool pref = (u + 1 < u1);

        if (newq) {
            if (qcur >= 0) flush_O(sm, O, b, qcur, mwarp, wcol, lane, tid);
            #pragma unroll
            for (int e = 0; e < 4; e++) {
                int i = e * 256 + tid, row = i >> 3, ch = i & 7;
                cp16(smb + A_OFF + row * 144 + ch * 16,
                     g_a + (size_t)(q * 128 + row) * 64 + ch * 8);
            }
            cp_commit();
            qcur = q;
        }
        if (pref)
            issue_chunk(smb, ((u + 1) & 1) ? B_OFF1 : B_OFF0, VT_OFF((u + 1) & 1),
                        64 * ((u + 1) & 127), tid);
        if (newq) {
            if (pref) asm volatile("cp.async.wait_group 1;" ::: "memory");
            else      asm volatile("cp.async.wait_group 0;" ::: "memory");
            __syncthreads();
            int rowa = mwarp + (lane & 15), offa = (lane >> 4) * 16;
            #pragma unroll
            for (int rt = 0; rt < 2; rt++)
                #pragma unroll
                for (int kt = 0; kt < 4; kt++)
                    ldsm_x4(afr[rt][kt][0], afr[rt][kt][1], afr[rt][kt][2], afr[rt][kt][3],
                            smb + A_OFF + (rowa + rt * 16) * 144 + kt * 32 + offa);
            #pragma unroll
            for (int rt = 0; rt < 2; rt++)
                #pragma unroll
                for (int e = 0; e < 4; e++) O[rt][e] = 0.f;
        }

        // ---- main GEMM on buffer p ----
        uint32_t boff = p ? B_OFF1 : B_OFF0;
        float acc[2][8][4];
        #pragma unroll
        for (int rt = 0; rt < 2; rt++)
            #pragma unroll
            for (int ct = 0; ct < 8; ct++)
                #pragma unroll
                for (int e = 0; e < 4; e++) acc[rt][ct][e] = 0.f;

        #pragma unroll
        for (int kt = 0; kt < 4; kt++) {
            uint32_t bfr[8][2];
            #pragma unroll
            for (int cp2 = 0; cp2 < 4; cp2++) {
                uint32_t r0, r1, r2, r3;
                ldsm_x4(r0, r1, r2, r3,
                        smb + boff + (brow_l + cp2 * 16) * 144 + kt * 32 + boffk);
                bfr[2*cp2][0] = r0; bfr[2*cp2][1] = r1;
                bfr[2*cp2+1][0] = r2; bfr[2*cp2+1][1] = r3;
            }
            #pragma unroll
            for (int ct = 0; ct < 8; ct++)
                #pragma unroll
                for (int rt = 0; rt < 2; rt++)
                    mma16816(acc[rt][ct], afr[rt][kt], bfr[ct]);
        }

        // ---- convert acc -> P (fp16 exp(logit)) in per-warp smem ----
        __syncwarp();
        #pragma unroll
        for (int ct = 0; ct < 8; ct++) {
            int key = ct * 4 + (lane & 3);
            #pragma unroll
            for (int rt = 0; rt < 2; rt++) {
                int r = rt * 16 + (lane >> 2);
                float l0 = fmaf(acc[rt][ct][0], acc[rt][ct][0], acc[rt][ct][1] * acc[rt][ct][1]);
                float l1 = fmaf(acc[rt][ct][2], acc[rt][ct][2], acc[rt][ct][3] * acc[rt][ct][3]);
                sts16(pbase + r * 80 + key * 2, __expf(l0));
                sts16(pbase + (r + 8) * 80 + key * 2, __expf(l1));
            }
        }
        __syncwarp();

        // ---- P(32x32) x Vt(32x8) GEMM into persistent O ----
        uint32_t vtb = smb + VT_OFF(p);
        #pragma unroll
        for (int kt2 = 0; kt2 < 2; kt2++) {
            uint32_t bb[2];
            ldsm_x2(bb[0], bb[1],
                    vtb + (l4 & 7) * 144 + wcol * 64 + kt2 * 32 + (l4 >> 3) * 16);
            #pragma unroll
            for (int rt2 = 0; rt2 < 2; rt2++) {
                uint32_t a4[4];
                ldsm_x4(a4[0], a4[1], a4[2], a4[3],
                        pbase + ((lane & 15) + rt2 * 16) * 80 + kt2 * 32 + (lane >> 4) * 16);
                mma16816(O[rt2], a4, bb);
            }
        }

        if (pref) {
            asm volatile("cp.async.wait_group 0;" ::: "memory");
            __syncthreads();
        }
    }
    flush_O(sm, O, b, qcur, mwarp, wcol, lane, tid);
}

__global__ void finalize_kernel(float* __restrict__ out)
{
    int i = blockIdx.x * blockDim.x + threadIdx.x;   // token
    int q = i >> 7, r = i & 127;
    int ca = (int)(((long long)(q * 128 + 1)   * GCTAS - 1) / NUNITS);
    int cb = (int)(((long long)(q * 128 + 128) * GCTAS - 1) / NUNITS);
    float a0 = 0.f, a1 = 0.f, a2 = 0.f, a3 = 0.f, a4 = 0.f, a5 = 0.f, dn = 0.f;
    for (int s = 0; s <= cb - ca; s++) {
        const float* p = g_part + ((size_t)(q * 8 + s) * 128 + r) * 8;
        a0 += p[0]; a1 += p[1]; a2 += p[2];
        a3 += p[3]; a4 += p[4]; a5 += p[5];
        dn += p[6];
    }
    float inv = 1.0f / dn;
    out[i * 6 + 0] = a0 * inv;
    out[i * 6 + 1] = a1 * inv;
    out[i * 6 + 2] = a2 * inv;
    out[i * 6 + 3] = a3 * inv;
    out[i * 6 + 4] = a4 * inv;
    out[i * 6 + 5] = a5 * inv;
}

extern "C" void kernel_launch(void* const* d_in, const int* in_sizes, int n_in,
                              void* d_out, int out_size)
{
    const float* x  = (const float*)d_in[0];
    const float* pq = (const float*)d_in[1];
    const float* pk = (const float*)d_in[2];
    const float* pv = (const float*)d_in[3];

    trig_kernel<<<1, 128>>>(pq, pk, pv);
    prep_kernel<<<(3 * NTOK) / 8, 256>>>(x);

    cudaFuncSetAttribute(attn_kernel, cudaFuncAttributeMaxDynamicSharedMemorySize, SMEM_TOTAL);
    attn_kernel<<<GCTAS, 256, SMEM_TOTAL>>>();

    finalize_kernel<<<NTOK / 256, 256>>>((float*)d_out);
}

// round 12
// speedup vs baseline: 1.7560x; 1.7560x over previous
#include <cuda_runtime.h>
#include <cuda_fp16.h>
#include <cstdint>

typedef unsigned long long u64;

#define NTOK 8192
#define GCTAS 296
#define NUNITS 8192                      // 64 qtiles * 128 chunks

// ---- smem layout (bytes) ----
#define A_OFF    0                       // 128 rows x 128B phi (pitch 144)
#define B_OFF0   18432
#define B_OFF1   36864                   // psi tiles, 128 rows x 128B (pitch 144)
#define VT_OFF(p) (55296 + (p) * 1152)   // 8 rows x 128B (pitch 144)
#define P_OFF    57600                   // 8 warps x (32 rows x 80B) = 20480
#define RED_OFF  78080                   // 128 x 8 floats
#define SMEM_TOTAL 82176                 // x2 CTAs = 164352 <= 228KB carveout

// ---------------- device scratch ----------------
__device__ __align__(16) __half g_a [NTOK * 64];    // phi_i (real, K=64)
__device__ __align__(16) __half g_b [NTOK * 128];   // rows 2j: Re(psi_j), 2j+1: Im(psi_j)
__device__ __align__(16) __half g_vt[8 * NTOK];     // rows 0-5: <Z_q>, row6: ones, row7: 0
__device__ float  g_part[(size_t)64 * 8 * 128 * 8]; // [qtile][slot(8)][tok][8]
__device__ float2 g_trig[3 * 24];

// ---------------- PTX helpers ----------------
__device__ __forceinline__ uint32_t smem_u32(const void* p) {
    uint32_t a;
    asm("{ .reg .u64 t; cvta.to.shared.u64 t, %1; cvt.u32.u64 %0, t; }" : "=r"(a) : "l"(p));
    return a;
}
__device__ __forceinline__ void cp16(uint32_t s, const void* g) {
    asm volatile("cp.async.cg.shared.global [%0], [%1], 16;" :: "r"(s), "l"(g));
}
__device__ __forceinline__ void cp_commit() { asm volatile("cp.async.commit_group;"); }

__device__ __forceinline__ void ldsm_x4(uint32_t& r0, uint32_t& r1, uint32_t& r2, uint32_t& r3, uint32_t a) {
    asm volatile("ldmatrix.sync.aligned.m8n8.x4.shared.b16 {%0,%1,%2,%3}, [%4];"
                 : "=r"(r0), "=r"(r1), "=r"(r2), "=r"(r3) : "r"(a));
}
__device__ __forceinline__ void ldsm_x2(uint32_t& r0, uint32_t& r1, uint32_t a) {
    asm volatile("ldmatrix.sync.aligned.m8n8.x2.shared.b16 {%0,%1}, [%2];"
                 : "=r"(r0), "=r"(r1) : "r"(a));
}
__device__ __forceinline__ void mma16816(float* c, const uint32_t* a, const uint32_t* b) {
    asm volatile("mma.sync.aligned.m16n8k16.row.col.f32.f16.f16.f32 "
                 "{%0,%1,%2,%3}, {%4,%5,%6,%7}, {%8,%9}, {%0,%1,%2,%3};"
                 : "+f"(c[0]), "+f"(c[1]), "+f"(c[2]), "+f"(c[3])
                 : "r"(a[0]), "r"(a[1]), "r"(a[2]), "r"(a[3]), "r"(b[0]), "r"(b[1]));
}
__device__ __forceinline__ void sts16(uint32_t a, float v) {
    unsigned short u = __half_as_ushort(__float2half_rn(v));
    asm volatile("st.shared.b16 [%0], %1;" :: "r"(a), "h"(u));
}

// ---------------- quantum gates ----------------
__device__ __forceinline__ void ry_sc(float s, float c, int q, int lane,
        float& a0x, float& a0y, float& a1x, float& a1y)
{
    if (q == 5) {
        float n0x = c*a0x - s*a1x, n0y = c*a0y - s*a1y;
        float n1x = s*a0x + c*a1x, n1y = s*a0y + c*a1y;
        a0x = n0x; a0y = n0y; a1x = n1x; a1y = n1y;
    } else {
        int sh = 4 - q, m = 1 << sh;
        float o0x = __shfl_xor_sync(0xffffffffu, a0x, m);
        float o0y = __shfl_xor_sync(0xffffffffu, a0y, m);
        float o1x = __shfl_xor_sync(0xffffffffu, a1x, m);
        float o1y = __shfl_xor_sync(0xffffffffu, a1y, m);
        float sg = ((lane >> sh) & 1) ? s : -s;
        a0x = c*a0x + sg*o0x; a0y = c*a0y + sg*o0y;
        a1x = c*a1x + sg*o1x; a1y = c*a1y + sg*o1y;
    }
}

__device__ __forceinline__ void rz_sc(float s, float c, int q, int lane,
        float& a0x, float& a0y, float& a1x, float& a1y)
{
    if (q == 5) {
        float n0x = a0x*c + a0y*s, n0y = a0y*c - a0x*s;
        float n1x = a1x*c - a1y*s, n1y = a1y*c + a1x*s;
        a0x = n0x; a0y = n0y; a1x = n1x; a1y = n1y;
    } else {
        float t = ((lane >> (4 - q)) & 1) ? s : -s;
        float n0x = a0x*c - a0y*t, n0y = a0y*c + a0x*t;
        float n1x = a1x*c - a1y*t, n1y = a1y*c + a1x*t;
        a0x = n0x; a0y = n0y; a1x = n1x; a1y = n1y;
    }
}

__device__ __forceinline__ void cnot_ll(int csh, int tmask, int lane,
        float& a0x, float& a0y, float& a1x, float& a1y)
{
    float o0x = __shfl_xor_sync(0xffffffffu, a0x, tmask);
    float o0y = __shfl_xor_sync(0xffffffffu, a0y, tmask);
    float o1x = __shfl_xor_sync(0xffffffffu, a1x, tmask);
    float o1y = __shfl_xor_sync(0xffffffffu, a1y, tmask);
    if ((lane >> csh) & 1) { a0x = o0x; a0y = o0y; a1x = o1x; a1y = o1y; }
}

__device__ __forceinline__ void pqc_fwd(const float2* trig, int lane,
        float& a0x, float& a0y, float& a1x, float& a1y)
{
    #pragma unroll
    for (int l = 0; l < 2; l++) {
        #pragma unroll
        for (int q = 0; q < 6; q++) {
            float2 ty = trig[(l * 6 + q) * 2 + 0];
            ry_sc(ty.x, ty.y, q, lane, a0x, a0y, a1x, a1y);
            float2 tz = trig[(l * 6 + q) * 2 + 1];
            rz_sc(tz.x, tz.y, q, lane, a0x, a0y, a1x, a1y);
        }
        cnot_ll(4, 8, lane, a0x, a0y, a1x, a1y);
        cnot_ll(3, 4, lane, a0x, a0y, a1x, a1y);
        cnot_ll(2, 2, lane, a0x, a0y, a1x, a1y);
        cnot_ll(1, 1, lane, a0x, a0y, a1x, a1y);
        if (lane & 1) {
            float t;
            t = a0x; a0x = a1x; a1x = t;
            t = a0y; a0y = a1y; a1y = t;
        }
        a1x = __shfl_xor_sync(0xffffffffu, a1x, 16);
        a1y = __shfl_xor_sync(0xffffffffu, a1y, 16);
    }
}

__device__ __forceinline__ void pqc_inv(const float2* trig, int lane,
        float& a0x, float& a0y, float& a1x, float& a1y)
{
    #pragma unroll
    for (int l = 1; l >= 0; l--) {
        a1x = __shfl_xor_sync(0xffffffffu, a1x, 16);
        a1y = __shfl_xor_sync(0xffffffffu, a1y, 16);
        if (lane & 1) {
            float t;
            t = a0x; a0x = a1x; a1x = t;
            t = a0y; a0y = a1y; a1y = t;
        }
        cnot_ll(1, 1, lane, a0x, a0y, a1x, a1y);
        cnot_ll(2, 2, lane, a0x, a0y, a1x, a1y);
        cnot_ll(3, 4, lane, a0x, a0y, a1x, a1y);
        cnot_ll(4, 8, lane, a0x, a0y, a1x, a1y);
        #pragma unroll
        for (int q = 0; q < 6; q++) {
            float2 tz = trig[(l * 6 + q) * 2 + 1];
            rz_sc(-tz.x, tz.y, q, lane, a0x, a0y, a1x, a1y);
            float2 ty = trig[(l * 6 + q) * 2 + 0];
            ry_sc(-ty.x, ty.y, q, lane, a0x, a0y, a1x, a1y);
        }
    }
}

__global__ void trig_kernel(const float* __restrict__ pq,
                            const float* __restrict__ pk,
                            const float* __restrict__ pv)
{
    int i = threadIdx.x;
    if (i < 72) {
        int set = i / 24, r = i % 24;
        const float* p = (set == 0) ? pq : (set == 1) ? pk : pv;
        float s, c;
        sincosf(0.5f * p[r], &s, &c);
        g_trig[i] = make_float2(s, c);
    }
}

__global__ void prep_kernel(const float* __restrict__ x)
{
    int gw   = (blockIdx.x * blockDim.x + threadIdx.x) >> 5;
    int lane = threadIdx.x & 31;
    int set  = gw >> 13;            // 0=Q(phi), 1=K(psi), 2=V
    int tok  = gw & (NTOK - 1);

    float a0x = (lane == 0) ? 1.f : 0.f, a0y = 0.f, a1x = 0.f, a1y = 0.f;

    #pragma unroll
    for (int q = 0; q < 6; q++) {
        float s, c;
        sincosf(0.5f * x[tok * 6 + q], &s, &c);
        ry_sc(s, c, q, lane, a0x, a0y, a1x, a1y);
    }

    if (set == 0) {
        ((__half2*)g_a)[tok * 32 + lane] = __floats2half2_rn(a0x, a1x);
    } else if (set == 1) {
        pqc_fwd(g_trig + 24, lane, a0x, a0y, a1x, a1y);   // K-PQC
        pqc_inv(g_trig + 0,  lane, a0x, a0y, a1x, a1y);   // inverse Q-PQC
        ((__half2*)g_b)[(tok * 2 + 0) * 32 + lane] = __floats2half2_rn(a0x, a1x);
        ((__half2*)g_b)[(tok * 2 + 1) * 32 + lane] = __floats2half2_rn(a0y, a1y);
    } else {
        pqc_fwd(g_trig + 48, lane, a0x, a0y, a1x, a1y);   // V-PQC
        float p0 = a0x*a0x + a0y*a0y;
        float p1 = a1x*a1x + a1y*a1y;
        int d0 = lane * 2, d1 = lane * 2 + 1;
        #pragma unroll
        for (int q = 0; q < 6; q++) {
            float s0 = ((d0 >> (5 - q)) & 1) ? -1.f : 1.f;
            float s1 = ((d1 >> (5 - q)) & 1) ? -1.f : 1.f;
            float z = s0 * p0 + s1 * p1;
            #pragma unroll
            for (int o = 16; o; o >>= 1) z += __shfl_xor_sync(0xffffffffu, z, o);
            if (lane == 0) g_vt[q * NTOK + tok] = __float2half_rn(z);
        }
        if (lane == 0) {
            g_vt[6 * NTOK + tok] = __float2half_rn(1.f);   // ones row -> den
            g_vt[7 * NTOK + tok] = __float2half_rn(0.f);
        }
    }
}

// ---------------- fused attention ----------------
extern __shared__ char smx[];

// one 64-key chunk: 128 psi col-rows (16KB) + Vt 8 rows x 128B (1KB)
__device__ __forceinline__ void issue_chunk(uint32_t smb, uint32_t boff, uint32_t vtoff,
                                            int kb, int tid)
{
    #pragma unroll
    for (int it = 0; it < 5; it++) {
        int i = it * 256 + tid;
        if (i < 1024) {
            int row = i >> 3, ch = i & 7;
            cp16(smb + boff + row * 144 + ch * 16,
                 g_b + (size_t)(kb * 2 + row) * 64 + ch * 8);
        } else if (i < 1088) {
            int j = i - 1024, row = j >> 3, ch = j & 7;
            cp16(smb + vtoff + row * 144 + ch * 16,
                 g_vt + (size_t)row * NTOK + kb + ch * 8);
        }
    }
    cp_commit();
}

__device__ __forceinline__ void flush_O(char* sm, float O[2][4], int b, int q,
                                        int mwarp, int wcol, int lane, int tid)
{
    float2* red = (float2*)(sm + RED_OFF);
    __syncthreads();
    int r0 = mwarp + (lane >> 2);
    int cc = lane & 3;
    if (wcol == 0) {
        #pragma unroll
        for (int rt = 0; rt < 2; rt++) {
            red[(r0 + rt * 16) * 4 + cc]     = make_float2(O[rt][0], O[rt][1]);
            red[(r0 + rt * 16 + 8) * 4 + cc] = make_float2(O[rt][2], O[rt][3]);
        }
    }
    __syncthreads();
    if (wcol == 1) {
        #pragma unroll
        for (int rt = 0; rt < 2; rt++) {
            float2 v0 = red[(r0 + rt * 16) * 4 + cc];
            v0.x += O[rt][0]; v0.y += O[rt][1];
            red[(r0 + rt * 16) * 4 + cc] = v0;
            float2 v1 = red[(r0 + rt * 16 + 8) * 4 + cc];
            v1.x += O[rt][2]; v1.y += O[rt][3];
            red[(r0 + rt * 16 + 8) * 4 + cc] = v1;
        }
    }
    __syncthreads();
    if (tid < 128) {
        int slot = b - (int)(((long long)(q * 128 + 1) * GCTAS - 1) / NUNITS);
        const float4* src = (const float4*)((const float*)(sm + RED_OFF) + tid * 8);
        float4* dst = (float4*)(g_part + ((size_t)(q * 8 + slot) * 128 + tid) * 8);
        dst[0] = src[0]; dst[1] = src[1];
    }
}

__global__ void __launch_bounds__(256, 2) attn_kernel()
{
    char* sm = smx;
    uint32_t smb = smem_u32(sm);
    int tid  = threadIdx.x;
    int wid  = tid >> 5, lane = tid & 31;
    int wrow = wid & 3, wcol = wid >> 2;      // warp grid 4x2
    int mwarp = wrow * 32;
    int b = blockIdx.x;
    int u0 = (int)(((long long)NUNITS * b) / GCTAS);
    int u1 = (int)(((long long)NUNITS * (b + 1)) / GCTAS);

    uint32_t pbase = smb + P_OFF + wid * 2560;

    // prologue: prefetch chunk u0 into its parity buffer
    {
        int p0 = u0 & 1;
        issue_chunk(smb, p0 ? B_OFF1 : B_OFF0, VT_OFF(p0), 64 * (u0 & 127), tid);
    }

    uint32_t afr[2][4][4];
    float O[2][4];
    int qcur = -1;
    int brow_l = wcol * 64 + (lane >> 4) * 8 + (lane & 7);
    int boffk  = ((lane >> 3) & 1) * 16;
    int l4 = lane & 15;

    for (int u = u0; u < u1; u++) {
        int q = u >> 7, p = u & 1;
        bool newq = (q != qcur);
        bool pref = (u + 1 < u1);

        if (newq) {
            if (qcur >= 0) flush_O(sm, O, b, qcur, mwarp, wcol, lane, tid);
            #pragma unroll
            for (int e = 0; e < 4; e++) {
                int i = e * 256 + tid, row = i >> 3, ch = i & 7;
                cp16(smb + A_OFF + row * 144 + ch * 16,
                     g_a + (size_t)(q * 128 + row) * 64 + ch * 8);
            }
            cp_commit();
            qcur = q;
        }
        if (pref)
            issue_chunk(smb, ((u + 1) & 1) ? B_OFF1 : B_OFF0, VT_OFF((u + 1) & 1),
                        64 * ((u + 1) & 127), tid);
        if (newq) {
            if (pref) asm volatile("cp.async.wait_group 1;" ::: "memory");
            else      asm volatile("cp.async.wait_group 0;" ::: "memory");
            __syncthreads();
            int rowa = mwarp + (lane & 15), offa = (lane >> 4) * 16;
            #pragma unroll
            for (int rt = 0; rt < 2; rt++)
                #pragma unroll
                for (int kt = 0; kt < 4; kt++)
                    ldsm_x4(afr[rt][kt][0], afr[rt][kt][1], afr[rt][kt][2], afr[rt][kt][3],
                            smb + A_OFF + (rowa + rt * 16) * 144 + kt * 32 + offa);
            #pragma unroll
            for (int rt = 0; rt < 2; rt++)
                #pragma unroll
                for (int e = 0; e < 4; e++) O[rt][e] = 0.f;
        }

        // ---- main GEMM on buffer p, split into two 16-key halves ----
        uint32_t boff = p ? B_OFF1 : B_OFF0;
        #pragma unroll
        for (int h = 0; h < 2; h++) {
            float acc[2][4][4];
            #pragma unroll
            for (int rt = 0; rt < 2; rt++)
                #pragma unroll
                for (int ct = 0; ct < 4; ct++)
                    #pragma unroll
                    for (int e = 0; e < 4; e++) acc[rt][ct][e] = 0.f;

            #pragma unroll
            for (int kt = 0; kt < 4; kt++) {
                uint32_t bfr[4][2];
                #pragma unroll
                for (int cp2 = 0; cp2 < 2; cp2++) {
                    uint32_t r0, r1, r2, r3;
                    ldsm_x4(r0, r1, r2, r3,
                            smb + boff + (brow_l + (2 * h + cp2) * 16) * 144 + kt * 32 + boffk);
                    bfr[2*cp2][0] = r0; bfr[2*cp2][1] = r1;
                    bfr[2*cp2+1][0] = r2; bfr[2*cp2+1][1] = r3;
                }
                #pragma unroll
                for (int ct = 0; ct < 4; ct++)
                    #pragma unroll
                    for (int rt = 0; rt < 2; rt++)
                        mma16816(acc[rt][ct], afr[rt][kt], bfr[ct]);
            }

            // convert this half's acc -> P (keys h*16 .. h*16+15)
            #pragma unroll
            for (int ct = 0; ct < 4; ct++) {
                int key = h * 16 + ct * 4 + (lane & 3);
                #pragma unroll
                for (int rt = 0; rt < 2; rt++) {
                    int r = rt * 16 + (lane >> 2);
                    float l0 = fmaf(acc[rt][ct][0], acc[rt][ct][0], acc[rt][ct][1] * acc[rt][ct][1]);
                    float l1 = fmaf(acc[rt][ct][2], acc[rt][ct][2], acc[rt][ct][3] * acc[rt][ct][3]);
                    sts16(pbase + r * 80 + key * 2, __expf(l0));
                    sts16(pbase + (r + 8) * 80 + key * 2, __expf(l1));
                }
            }
        }
        __syncwarp();

        // ---- P(32x32) x Vt(32x8) GEMM into persistent O ----
        uint32_t vtb = smb + VT_OFF(p);
        #pragma unroll
        for (int kt2 = 0; kt2 < 2; kt2++) {
            uint32_t bb[2];
            ldsm_x2(bb[0], bb[1],
                    vtb + (l4 & 7) * 144 + wcol * 64 + kt2 * 32 + (l4 >> 3) * 16);
            #pragma unroll
            for (int rt2 = 0; rt2 < 2; rt2++) {
                uint32_t a4[4];
                ldsm_x4(a4[0], a4[1], a4[2], a4[3],
                        pbase + ((lane & 15) + rt2 * 16) * 80 + kt2 * 32 + (lane >> 4) * 16);
                mma16816(O[rt2], a4, bb);
            }
        }

        if (pref) {
            asm volatile("cp.async.wait_group 0;" ::: "memory");
            __syncthreads();
        }
    }
    flush_O(sm, O, b, qcur, mwarp, wcol, lane, tid);
}

__global__ void finalize_kernel(float* __restrict__ out)
{
    int i = blockIdx.x * blockDim.x + threadIdx.x;   // token
    int q = i >> 7, r = i & 127;
    int ca = (int)(((long long)(q * 128 + 1)   * GCTAS - 1) / NUNITS);
    int cb = (int)(((long long)(q * 128 + 128) * GCTAS - 1) / NUNITS);
    float a0 = 0.f, a1 = 0.f, a2 = 0.f, a3 = 0.f, a4 = 0.f, a5 = 0.f, dn = 0.f;
    for (int s = 0; s <= cb - ca; s++) {
        const float* p = g_part + ((size_t)(q * 8 + s) * 128 + r) * 8;
        a0 += p[0]; a1 += p[1]; a2 += p[2];
        a3 += p[3]; a4 += p[4]; a5 += p[5];
        dn += p[6];
    }
    float inv = 1.0f / dn;
    out[i * 6 + 0] = a0 * inv;
    out[i * 6 + 1] = a1 * inv;
    out[i * 6 + 2] = a2 * inv;
    out[i * 6 + 3] = a3 * inv;
    out[i * 6 + 4] = a4 * inv;
    out[i * 6 + 5] = a5 * inv;
}

extern "C" void kernel_launch(void* const* d_in, const int* in_sizes, int n_in,
                              void* d_out, int out_size)
{
    const float* x  = (const float*)d_in[0];
    const float* pq = (const float*)d_in[1];
    const float* pk = (const float*)d_in[2];
    const float* pv = (const float*)d_in[3];

    trig_kernel<<<1, 128>>>(pq, pk, pv);
    prep_kernel<<<(3 * NTOK) / 8, 256>>>(x);

    cudaFuncSetAttribute(attn_kernel, cudaFuncAttributeMaxDynamicSharedMemorySize, SMEM_TOTAL);
    attn_kernel<<<GCTAS, 256, SMEM_TOTAL>>>();

    finalize_kernel<<<NTOK / 256, 256>>>((float*)d_out);
}

// round 13
// speedup vs baseline: 1.8841x; 1.0730x over previous
#include <cuda_runtime.h>
#include <cuda_fp16.h>
#include <cstdint>

typedef unsigned long long u64;

#define NTOK 8192
#define GCTAS 296
#define NUNITS 8192                      // 64 qtiles * 128 chunks

// ---- attn smem layout (bytes) ----
#define A_OFF    0                       // 128 rows x 128B phi (pitch 144)
#define B_OFF0   18432
#define B_OFF1   36864                   // psi tiles, 128 rows x 128B (pitch 144)
#define VT_OFF(p) (55296 + (p) * 1152)   // 8 rows x 128B (pitch 144)
#define P_OFF    57600                   // 8 warps x (32 rows x 80B) = 20480
#define RED_OFF  78080                   // 128 x 8 floats
#define SMEM_TOTAL 82176                 // x2 CTAs <= 228KB carveout

// ---- prep_gemm smem layout ----
#define PG_A   0
#define PG_B   18432
#define PG_T   36864                     // psi: 256 rows x 144B = 36864
#define PG_P   36864                     // V: 8 warps x 2560
#define PG_ST  57344                     // 8 x 144
#define PG_RED 58496                     // 128 x 8 floats
#define SMEM_PREP 73728

// ---------------- device scratch ----------------
__device__ __align__(16) __half g_a [NTOK * 64];    // phi_i (real, K=64)
__device__ __align__(16) __half g_b [NTOK * 128];   // rows 2j: Re(psi_j), 2j+1: Im(psi_j)
__device__ __align__(16) __half g_vt[8 * NTOK];     // rows 0-5: <Z_q>, row6: ones, row7: 0
__device__ __align__(16) __half g_bm[128 * 64];     // M = Pq^H Pk  (row 2a+r = Re/Im amp a, col d)
__device__ __align__(16) __half g_wv[128 * 64];     // Pv
__device__ float g_part[(size_t)64 * 8 * 128 * 8];  // [qtile][slot(8)][tok][8]

// ---------------- PTX helpers ----------------
__device__ __forceinline__ uint32_t smem_u32(const void* p) {
    uint32_t a;
    asm("{ .reg .u64 t; cvta.to.shared.u64 t, %1; cvt.u32.u64 %0, t; }" : "=r"(a) : "l"(p));
    return a;
}
__device__ __forceinline__ void cp16(uint32_t s, const void* g) {
    asm volatile("cp.async.cg.shared.global [%0], [%1], 16;" :: "r"(s), "l"(g));
}
__device__ __forceinline__ void cp_commit() { asm volatile("cp.async.commit_group;"); }

__device__ __forceinline__ void ldsm_x4(uint32_t& r0, uint32_t& r1, uint32_t& r2, uint32_t& r3, uint32_t a) {
    asm volatile("ldmatrix.sync.aligned.m8n8.x4.shared.b16 {%0,%1,%2,%3}, [%4];"
                 : "=r"(r0), "=r"(r1), "=r"(r2), "=r"(r3) : "r"(a));
}
__device__ __forceinline__ void ldsm_x2(uint32_t& r0, uint32_t& r1, uint32_t a) {
    asm volatile("ldmatrix.sync.aligned.m8n8.x2.shared.b16 {%0,%1}, [%2];"
                 : "=r"(r0), "=r"(r1) : "r"(a));
}
__device__ __forceinline__ void mma16816(float* c, const uint32_t* a, const uint32_t* b) {
    asm volatile("mma.sync.aligned.m16n8k16.row.col.f32.f16.f16.f32 "
                 "{%0,%1,%2,%3}, {%4,%5,%6,%7}, {%8,%9}, {%0,%1,%2,%3};"
                 : "+f"(c[0]), "+f"(c[1]), "+f"(c[2]), "+f"(c[3])
                 : "r"(a[0]), "r"(a[1]), "r"(a[2]), "r"(a[3]), "r"(b[0]), "r"(b[1]));
}
__device__ __forceinline__ void sts16(uint32_t a, float v) {
    unsigned short u = __half_as_ushort(__float2half_rn(v));
    asm volatile("st.shared.b16 [%0], %1;" :: "r"(a), "h"(u));
}

// ---------------- quantum gates (warp-distributed 64-amp state) ----------------
__device__ __forceinline__ void ry_sc(float s, float c, int q, int lane,
        float& a0x, float& a0y, float& a1x, float& a1y)
{
    if (q == 5) {
        float n0x = c*a0x - s*a1x, n0y = c*a0y - s*a1y;
        float n1x = s*a0x + c*a1x, n1y = s*a0y + c*a1y;
        a0x = n0x; a0y = n0y; a1x = n1x; a1y = n1y;
    } else {
        int sh = 4 - q, m = 1 << sh;
        float o0x = __shfl_xor_sync(0xffffffffu, a0x, m);
        float o0y = __shfl_xor_sync(0xffffffffu, a0y, m);
        float o1x = __shfl_xor_sync(0xffffffffu, a1x, m);
        float o1y = __shfl_xor_sync(0xffffffffu, a1y, m);
        float sg = ((lane >> sh) & 1) ? s : -s;
        a0x = c*a0x + sg*o0x; a0y = c*a0y + sg*o0y;
        a1x = c*a1x + sg*o1x; a1y = c*a1y + sg*o1y;
    }
}

__device__ __forceinline__ void rz_sc(float s, float c, int q, int lane,
        float& a0x, float& a0y, float& a1x, float& a1y)
{
    if (q == 5) {
        float n0x = a0x*c + a0y*s, n0y = a0y*c - a0x*s;
        float n1x = a1x*c - a1y*s, n1y = a1y*c + a1x*s;
        a0x = n0x; a0y = n0y; a1x = n1x; a1y = n1y;
    } else {
        float t = ((lane >> (4 - q)) & 1) ? s : -s;
        float n0x = a0x*c - a0y*t, n0y = a0y*c + a0x*t;
        float n1x = a1x*c - a1y*t, n1y = a1y*c + a1x*t;
        a0x = n0x; a0y = n0y; a1x = n1x; a1y = n1y;
    }
}

__device__ __forceinline__ void cnot_ll(int csh, int tmask, int lane,
        float& a0x, float& a0y, float& a1x, float& a1y)
{
    float o0x = __shfl_xor_sync(0xffffffffu, a0x, tmask);
    float o0y = __shfl_xor_sync(0xffffffffu, a0y, tmask);
    float o1x = __shfl_xor_sync(0xffffffffu, a1x, tmask);
    float o1y = __shfl_xor_sync(0xffffffffu, a1y, tmask);
    if ((lane >> csh) & 1) { a0x = o0x; a0y = o0y; a1x = o1x; a1y = o1y; }
}

__device__ __forceinline__ void pqc_fwd(const float2* trig, int lane,
        float& a0x, float& a0y, float& a1x, float& a1y)
{
    #pragma unroll
    for (int l = 0; l < 2; l++) {
        #pragma unroll
        for (int q = 0; q < 6; q++) {
            float2 ty = trig[(l * 6 + q) * 2 + 0];
            ry_sc(ty.x, ty.y, q, lane, a0x, a0y, a1x, a1y);
            float2 tz = trig[(l * 6 + q) * 2 + 1];
            rz_sc(tz.x, tz.y, q, lane, a0x, a0y, a1x, a1y);
        }
        cnot_ll(4, 8, lane, a0x, a0y, a1x, a1y);
        cnot_ll(3, 4, lane, a0x, a0y, a1x, a1y);
        cnot_ll(2, 2, lane, a0x, a0y, a1x, a1y);
        cnot_ll(1, 1, lane, a0x, a0y, a1x, a1y);
        if (lane & 1) {
            float t;
            t = a0x; a0x = a1x; a1x = t;
            t = a0y; a0y = a1y; a1y = t;
        }
        a1x = __shfl_xor_sync(0xffffffffu, a1x, 16);
        a1y = __shfl_xor_sync(0xffffffffu, a1y, 16);
    }
}

__device__ __forceinline__ void pqc_inv(const float2* trig, int lane,
        float& a0x, float& a0y, float& a1x, float& a1y)
{
    #pragma unroll
    for (int l = 1; l >= 0; l--) {
        a1x = __shfl_xor_sync(0xffffffffu, a1x, 16);
        a1y = __shfl_xor_sync(0xffffffffu, a1y, 16);
        if (lane & 1) {
            float t;
            t = a0x; a0x = a1x; a1x = t;
            t = a0y; a0y = a1y; a1y = t;
        }
        cnot_ll(1, 1, lane, a0x, a0y, a1x, a1y);
        cnot_ll(2, 2, lane, a0x, a0y, a1x, a1y);
        cnot_ll(3, 4, lane, a0x, a0y, a1x, a1y);
        cnot_ll(4, 8, lane, a0x, a0y, a1x, a1y);
        #pragma unroll
        for (int q = 0; q < 6; q++) {
            float2 tz = trig[(l * 6 + q) * 2 + 1];
            rz_sc(-tz.x, tz.y, q, lane, a0x, a0y, a1x, a1y);
            float2 ty = trig[(l * 6 + q) * 2 + 0];
            ry_sc(-ty.x, ty.y, q, lane, a0x, a0y, a1x, a1y);
        }
    }
}

// ---------------- basis: materialize M = Pq^H Pk and Pv as fp16 B-matrices ----------------
__global__ void basis_kernel(const float* __restrict__ pq,
                             const float* __restrict__ pk,
                             const float* __restrict__ pv)
{
    __shared__ float2 strig[72];
    int tid = threadIdx.x;
    if (tid < 72) {
        int set = tid / 24, r = tid % 24;
        const float* p = (set == 0) ? pq : (set == 1) ? pk : pv;
        float s, c;
        sincosf(0.5f * p[r], &s, &c);
        strig[tid] = make_float2(s, c);
    }
    __syncthreads();

    int gw   = blockIdx.x * 8 + (tid >> 5);   // 0..127
    int lane = tid & 31;
    int d    = gw & 63;

    float a0x = (2 * lane == d) ? 1.f : 0.f, a0y = 0.f;
    float a1x = (2 * lane + 1 == d) ? 1.f : 0.f, a1y = 0.f;

    if (gw < 64) {
        pqc_fwd(strig + 24, lane, a0x, a0y, a1x, a1y);   // K-PQC
        pqc_inv(strig + 0,  lane, a0x, a0y, a1x, a1y);   // inverse Q-PQC
        g_bm[(4 * lane + 0) * 64 + d] = __float2half_rn(a0x);
        g_bm[(4 * lane + 1) * 64 + d] = __float2half_rn(a0y);
        g_bm[(4 * lane + 2) * 64 + d] = __float2half_rn(a1x);
        g_bm[(4 * lane + 3) * 64 + d] = __float2half_rn(a1y);
    } else {
        pqc_fwd(strig + 48, lane, a0x, a0y, a1x, a1y);   // V-PQC
        g_wv[(4 * lane + 0) * 64 + d] = __float2half_rn(a0x);
        g_wv[(4 * lane + 1) * 64 + d] = __float2half_rn(a0y);
        g_wv[(4 * lane + 2) * 64 + d] = __float2half_rn(a1x);
        g_wv[(4 * lane + 3) * 64 + d] = __float2half_rn(a1y);
    }
}

// ---------------- phi: tensor-product embedding state, one thread per token ----------------
__global__ void phi_kernel(const float* __restrict__ x)
{
    __shared__ __half buf[256 * 72];
    int tl = threadIdx.x;
    int tok = blockIdx.x * 256 + tl;

    float f[6][2];
    #pragma unroll
    for (int q = 0; q < 6; q++) {
        float s, c;
        __sincosf(0.5f * x[tok * 6 + q], &s, &c);
        f[q][0] = c; f[q][1] = s;
    }
    float t01[4], t23[4], t45[4];
    #pragma unroll
    for (int b = 0; b < 4; b++) {
        t01[b] = f[0][b >> 1] * f[1][b & 1];
        t23[b] = f[2][b >> 1] * f[3][b & 1];
        t45[b] = f[4][b >> 1] * f[5][b & 1];
    }
    #pragma unroll
    for (int d = 0; d < 64; d++)
        buf[tl * 72 + d] = __float2half_rn(t01[d >> 4] * t23[(d >> 2) & 3] * t45[d & 3]);
    __syncthreads();

    uint4* dst = (uint4*)(g_a + (size_t)(blockIdx.x * 256 + tl) * 64);
    #pragma unroll
    for (int k = 0; k < 8; k++)
        dst[k] = *(uint4*)(buf + tl * 72 + k * 8);
}

// ---------------- prep GEMM: psi = M phi  /  V from |Pv phi|^2 ----------------
extern __shared__ char smx[];

__global__ void __launch_bounds__(256) prep_gemm_kernel()
{
    char* sm = smx;
    uint32_t smb = smem_u32(sm);
    int tid  = threadIdx.x;
    int wid  = tid >> 5, lane = tid & 31;
    int wrow = wid & 3, wcol = wid >> 2;
    int mwarp = wrow * 32;
    int qbase = blockIdx.x * 128;
    const __half* gB = blockIdx.y ? g_wv : g_bm;

    #pragma unroll
    for (int e = 0; e < 4; e++) {
        int i = e * 256 + tid, row = i >> 3, ch = i & 7;
        cp16(smb + PG_A + row * 144 + ch * 16, g_a + (size_t)(qbase + row) * 64 + ch * 8);
    }
    #pragma unroll
    for (int e = 0; e < 4; e++) {
        int i = e * 256 + tid, row = i >> 3, ch = i & 7;
        cp16(smb + PG_B + row * 144 + ch * 16, gB + (size_t)row * 64 + ch * 8);
    }
    cp_commit();
    if (blockIdx.y == 1) {   // signs matrix St[8][64] (row6,7 = 0)
        for (int i = tid; i < 512; i += 256) {
            int q = i >> 6, a = i & 63;
            float sg = (q < 6) ? (((a >> (5 - q)) & 1) ? -1.f : 1.f) : 0.f;
            *(__half*)(sm + PG_ST + q * 144 + a * 2) = __float2half_rn(sg);
        }
    }
    asm volatile("cp.async.wait_group 0;" ::: "memory");
    __syncthreads();

    // A fragments (K=64)
    uint32_t afr[2][4][4];
    {
        int rowa = mwarp + (lane & 15), offa = (lane >> 4) * 16;
        #pragma unroll
        for (int rt = 0; rt < 2; rt++)
            #pragma unroll
            for (int kt = 0; kt < 4; kt++)
                ldsm_x4(afr[rt][kt][0], afr[rt][kt][1], afr[rt][kt][2], afr[rt][kt][3],
                        smb + PG_A + (rowa + rt * 16) * 144 + kt * 32 + offa);
    }

    int brow_l = wcol * 64 + (lane >> 4) * 8 + (lane & 7);
    int boffk  = ((lane >> 3) & 1) * 16;
    int l4 = lane & 15;

    float acc[2][8][4];
    #pragma unroll
    for (int rt = 0; rt < 2; rt++)
        #pragma unroll
        for (int ct = 0; ct < 8; ct++)
            #pragma unroll
            for (int e = 0; e < 4; e++) acc[rt][ct][e] = 0.f;

    #pragma unroll
    for (int kt = 0; kt < 4; kt++) {
        uint32_t bfr[8][2];
        #pragma unroll
        for (int cp2 = 0; cp2 < 4; cp2++) {
            uint32_t r0, r1, r2, r3;
            ldsm_x4(r0, r1, r2, r3,
                    smb + PG_B + (brow_l + cp2 * 16) * 144 + kt * 32 + boffk);
            bfr[2*cp2][0] = r0; bfr[2*cp2][1] = r1;
            bfr[2*cp2+1][0] = r2; bfr[2*cp2+1][1] = r3;
        }
        #pragma unroll
        for (int ct = 0; ct < 8; ct++)
            #pragma unroll
            for (int rt = 0; rt < 2; rt++)
                mma16816(acc[rt][ct], afr[rt][kt], bfr[ct]);
    }

    if (blockIdx.y == 0) {
        // psi: C[j][2d+r] -> smem transpose -> g_b[(2j+r)][d]
        #pragma unroll
        for (int rt = 0; rt < 2; rt++)
            #pragma unroll
            for (int ct = 0; ct < 8; ct++) {
                int r0 = mwarp + rt * 16 + (lane >> 2);
                int d  = wcol * 32 + ct * 4 + (lane & 3);
                sts16(smb + PG_T + (2 * r0) * 144 + d * 2,       acc[rt][ct][0]);
                sts16(smb + PG_T + (2 * r0 + 1) * 144 + d * 2,   acc[rt][ct][1]);
                sts16(smb + PG_T + (2 * (r0 + 8)) * 144 + d * 2,     acc[rt][ct][2]);
                sts16(smb + PG_T + (2 * (r0 + 8) + 1) * 144 + d * 2, acc[rt][ct][3]);
            }
        __syncthreads();
        uint4* dst = (uint4*)(g_b + ((size_t)qbase * 2 + tid) * 64);
        #pragma unroll
        for (int k = 0; k < 8; k++)
            dst[k] = *(uint4*)(sm + PG_T + tid * 144 + k * 16);
    } else {
        // V: p = |w|^2 -> P-buf -> mini-GEMM with signs
        uint32_t pbase = smb + PG_P + wid * 2560;
        #pragma unroll
        for (int rt = 0; rt < 2; rt++)
            #pragma unroll
            for (int ct = 0; ct < 8; ct++) {
                int rl = rt * 16 + (lane >> 2);
                int dl = ct * 4 + (lane & 3);
                float p0 = fmaf(acc[rt][ct][0], acc[rt][ct][0], acc[rt][ct][1] * acc[rt][ct][1]);
                float p1 = fmaf(acc[rt][ct][2], acc[rt][ct][2], acc[rt][ct][3] * acc[rt][ct][3]);
                sts16(pbase + rl * 80 + dl * 2, p0);
                sts16(pbase + (rl + 8) * 80 + dl * 2, p1);
            }
        __syncwarp();
        float O[2][4];
        #pragma unroll
        for (int rt = 0; rt < 2; rt++)
            #pragma unroll
            for (int e = 0; e < 4; e++) O[rt][e] = 0.f;
        #pragma unroll
        for (int kt2 = 0; kt2 < 2; kt2++) {
            uint32_t bb[2];
            ldsm_x2(bb[0], bb[1],
                    smb + PG_ST + (l4 & 7) * 144 + wcol * 64 + kt2 * 32 + (l4 >> 3) * 16);
            #pragma unroll
            for (int rt2 = 0; rt2 < 2; rt2++) {
                uint32_t a4[4];
                ldsm_x4(a4[0], a4[1], a4[2], a4[3],
                        pbase + ((lane & 15) + rt2 * 16) * 80 + kt2 * 32 + (lane >> 4) * 16);
                mma16816(O[rt2], a4, bb);
            }
        }
        // combine warp col-halves, write g_vt
        float2* red = (float2*)(sm + PG_RED);
        __syncthreads();
        int r0 = mwarp + (lane >> 2), cc = lane & 3;
        if (wcol == 0) {
            #pragma unroll
            for (int rt = 0; rt < 2; rt++) {
                red[(r0 + rt * 16) * 4 + cc]     = make_float2(O[rt][0], O[rt][1]);
                red[(r0 + rt * 16 + 8) * 4 + cc] = make_float2(O[rt][2], O[rt][3]);
            }
        }
        __syncthreads();
        if (wcol == 1) {
            #pragma unroll
            for (int rt = 0; rt < 2; rt++) {
                float2 v0 = red[(r0 + rt * 16) * 4 + cc];
                v0.x += O[rt][0]; v0.y += O[rt][1];
                red[(r0 + rt * 16) * 4 + cc] = v0;
                float2 v1 = red[(r0 + rt * 16 + 8) * 4 + cc];
                v1.x += O[rt][2]; v1.y += O[rt][3];
                red[(r0 + rt * 16 + 8) * 4 + cc] = v1;
            }
        }
        __syncthreads();
        if (tid < 128) {
            int token = qbase + tid;
            const float* rp = (const float*)(sm + PG_RED) + tid * 8;
            #pragma unroll
            for (int q = 0; q < 6; q++)
                g_vt[q * NTOK + token] = __float2half_rn(rp[q]);
            g_vt[6 * NTOK + token] = __float2half_rn(1.f);
            g_vt[7 * NTOK + token] = __float2half_rn(0.f);
        }
    }
}

// ---------------- fused attention (unchanged from validated r12) ----------------
__device__ __forceinline__ void issue_chunk(uint32_t smb, uint32_t boff, uint32_t vtoff,
                                            int kb, int tid)
{
    #pragma unroll
    for (int it = 0; it < 5; it++) {
        int i = it * 256 + tid;
        if (i < 1024) {
            int row = i >> 3, ch = i & 7;
            cp16(smb + boff + row * 144 + ch * 16,
                 g_b + (size_t)(kb * 2 + row) * 64 + ch * 8);
        } else if (i < 1088) {
            int j = i - 1024, row = j >> 3, ch = j & 7;
            cp16(smb + vtoff + row * 144 + ch * 16,
                 g_vt + (size_t)row * NTOK + kb + ch * 8);
        }
    }
    cp_commit();
}

__device__ __forceinline__ void flush_O(char* sm, float O[2][4], int b, int q,
                                        int mwarp, int wcol, int lane, int tid)
{
    float2* red = (float2*)(sm + RED_OFF);
    __syncthreads();
    int r0 = mwarp + (lane >> 2);
    int cc = lane & 3;
    if (wcol == 0) {
        #pragma unroll
        for (int rt = 0; rt < 2; rt++) {
            red[(r0 + rt * 16) * 4 + cc]     = make_float2(O[rt][0], O[rt][1]);
            red[(r0 + rt * 16 + 8) * 4 + cc] = make_float2(O[rt][2], O[rt][3]);
        }
    }
    __syncthreads();
    if (wcol == 1) {
        #pragma unroll
        for (int rt = 0; rt < 2; rt++) {
            float2 v0 = red[(r0 + rt * 16) * 4 + cc];
            v0.x += O[rt][0]; v0.y += O[rt][1];
            red[(r0 + rt * 16) * 4 + cc] = v0;
            float2 v1 = red[(r0 + rt * 16 + 8) * 4 + cc];
            v1.x += O[rt][2]; v1.y += O[rt][3];
            red[(r0 + rt * 16 + 8) * 4 + cc] = v1;
        }
    }
    __syncthreads();
    if (tid < 128) {
        int slot = b - (int)(((long long)(q * 128 + 1) * GCTAS - 1) / NUNITS);
        const float4* src = (const float4*)((const float*)(sm + RED_OFF) + tid * 8);
        float4* dst = (float4*)(g_part + ((size_t)(q * 8 + slot) * 128 + tid) * 8);
        dst[0] = src[0]; dst[1] = src[1];
    }
}

__global__ void __launch_bounds__(256, 2) attn_kernel()
{
    char* sm = smx;
    uint32_t smb = smem_u32(sm);
    int tid  = threadIdx.x;
    int wid  = tid >> 5, lane = tid & 31;
    int wrow = wid & 3, wcol = wid >> 2;
    int mwarp = wrow * 32;
    int b = blockIdx.x;
    int u0 = (int)(((long long)NUNITS * b) / GCTAS);
    int u1 = (int)(((long long)NUNITS * (b + 1)) / GCTAS);

    uint32_t pbase = smb + P_OFF + wid * 2560;

    {
        int p0 = u0 & 1;
        issue_chunk(smb, p0 ? B_OFF1 : B_OFF0, VT_OFF(p0), 64 * (u0 & 127), tid);
    }

    uint32_t afr[2][4][4];
    float O[2][4];
    int qcur = -1;
    int brow_l = wcol * 64 + (lane >> 4) * 8 + (lane & 7);
    int boffk  = ((lane >> 3) & 1) * 16;
    int l4 = lane & 15;

    for (int u = u0; u < u1; u++) {
        int q = u >> 7, p = u & 1;
        bool newq = (q != qcur);
        bool pref = (u + 1 < u1);

        if (newq) {
            if (qcur >= 0) flush_O(sm, O, b, qcur, mwarp, wcol, lane, tid);
            #pragma unroll
            for (int e = 0; e < 4; e++) {
                int i = e * 256 + tid, row = i >> 3, ch = i & 7;
                cp16(smb + A_OFF + row * 144 + ch * 16,
                     g_a + (size_t)(q * 128 + row) * 64 + ch * 8);
            }
            cp_commit();
            qcur = q;
        }
        if (pref)
            issue_chunk(smb, ((u + 1) & 1) ? B_OFF1 : B_OFF0, VT_OFF((u + 1) & 1),
                        64 * ((u + 1) & 127), tid);
        if (newq) {
            if (pref) asm volatile("cp.async.wait_group 1;" ::: "memory");
            else      asm volatile("cp.async.wait_group 0;" ::: "memory");
            __syncthreads();
            int rowa = mwarp + (lane & 15), offa = (lane >> 4) * 16;
            #pragma unroll
            for (int rt = 0; rt < 2; rt++)
                #pragma unroll
                for (int kt = 0; kt < 4; kt++)
                    ldsm_x4(afr[rt][kt][0], afr[rt][kt][1], afr[rt][kt][2], afr[rt][kt][3],
                            smb + A_OFF + (rowa + rt * 16) * 144 + kt * 32 + offa);
            #pragma unroll
            for (int rt = 0; rt < 2; rt++)
                #pragma unroll
                for (int e = 0; e < 4; e++) O[rt][e] = 0.f;
        }

        uint32_t boff = p ? B_OFF1 : B_OFF0;
        #pragma unroll
        for (int h = 0; h < 2; h++) {
            float acc[2][4][4];
            #pragma unroll
            for (int rt = 0; rt < 2; rt++)
                #pragma unroll
                for (int ct = 0; ct < 4; ct++)
                    #pragma unroll
                    for (int e = 0; e < 4; e++) acc[rt][ct][e] = 0.f;

            #pragma unroll
            for (int kt = 0; kt < 4; kt++) {
                uint32_t bfr[4][2];
                #pragma unroll
                for (int cp2 = 0; cp2 < 2; cp2++) {
                    uint32_t r0, r1, r2, r3;
                    ldsm_x4(r0, r1, r2, r3,
                            smb + boff + (brow_l + (2 * h + cp2) * 16) * 144 + kt * 32 + boffk);
                    bfr[2*cp2][0] = r0; bfr[2*cp2][1] = r1;
                    bfr[2*cp2+1][0] = r2; bfr[2*cp2+1][1] = r3;
                }
                #pragma unroll
                for (int ct = 0; ct < 4; ct++)
                    #pragma unroll
                    for (int rt = 0; rt < 2; rt++)
                        mma16816(acc[rt][ct], afr[rt][kt], bfr[ct]);
            }

            #pragma unroll
            for (int ct = 0; ct < 4; ct++) {
                int key = h * 16 + ct * 4 + (lane & 3);
                #pragma unroll
                for (int rt = 0; rt < 2; rt++) {
                    int r = rt * 16 + (lane >> 2);
                    float l0 = fmaf(acc[rt][ct][0], acc[rt][ct][0], acc[rt][ct][1] * acc[rt][ct][1]);
                    float l1 = fmaf(acc[rt][ct][2], acc[rt][ct][2], acc[rt][ct][3] * acc[rt][ct][3]);
                    sts16(pbase + r * 80 + key * 2, __expf(l0));
                    sts16(pbase + (r + 8) * 80 + key * 2, __expf(l1));
                }
            }
        }
        __syncwarp();

        uint32_t vtb = smb + VT_OFF(p);
        #pragma unroll
        for (int kt2 = 0; kt2 < 2; kt2++) {
            uint32_t bb[2];
            ldsm_x2(bb[0], bb[1],
                    vtb + (l4 & 7) * 144 + wcol * 64 + kt2 * 32 + (l4 >> 3) * 16);
            #pragma unroll
            for (int rt2 = 0; rt2 < 2; rt2++) {
                uint32_t a4[4];
                ldsm_x4(a4[0], a4[1], a4[2], a4[3],
                        pbase + ((lane & 15) + rt2 * 16) * 80 + kt2 * 32 + (lane >> 4) * 16);
                mma16816(O[rt2], a4, bb);
            }
        }

        if (pref) {
            asm volatile("cp.async.wait_group 0;" ::: "memory");
            __syncthreads();
        }
    }
    flush_O(sm, O, b, qcur, mwarp, wcol, lane, tid);
}

__global__ void finalize_kernel(float* __restrict__ out)
{
    int i = blockIdx.x * blockDim.x + threadIdx.x;   // token
    int q = i >> 7, r = i & 127;
    int ca = (int)(((long long)(q * 128 + 1)   * GCTAS - 1) / NUNITS);
    int cb = (int)(((long long)(q * 128 + 128) * GCTAS - 1) / NUNITS);
    float a0 = 0.f, a1 = 0.f, a2 = 0.f, a3 = 0.f, a4 = 0.f, a5 = 0.f, dn = 0.f;
    for (int s = 0; s <= cb - ca; s++) {
        const float* p = g_part + ((size_t)(q * 8 + s) * 128 + r) * 8;
        a0 += p[0]; a1 += p[1]; a2 += p[2];
        a3 += p[3]; a4 += p[4]; a5 += p[5];
        dn += p[6];
    }
    float inv = 1.0f / dn;
    out[i * 6 + 0] = a0 * inv;
    out[i * 6 + 1] = a1 * inv;
    out[i * 6 + 2] = a2 * inv;
    out[i * 6 + 3] = a3 * inv;
    out[i * 6 + 4] = a4 * inv;
    out[i * 6 + 5] = a5 * inv;
}

extern "C" void kernel_launch(void* const* d_in, const int* in_sizes, int n_in,
                              void* d_out, int out_size)
{
    const float* x  = (const float*)d_in[0];
    const float* pq = (const float*)d_in[1];
    const float* pk = (const float*)d_in[2];
    const float* pv = (const float*)d_in[3];

    basis_kernel<<<16, 256>>>(pq, pk, pv);
    phi_kernel<<<NTOK / 256, 256>>>(x);

    cudaFuncSetAttribute(prep_gemm_kernel, cudaFuncAttributeMaxDynamicSharedMemorySize, SMEM_PREP);
    prep_gemm_kernel<<<dim3(64, 2), 256, SMEM_PREP>>>();

    cudaFuncSetAttribute(attn_kernel, cudaFuncAttributeMaxDynamicSharedMemorySize, SMEM_TOTAL);
    attn_kernel<<<GCTAS, 256, SMEM_TOTAL>>>();

    finalize_kernel<<<NTOK / 256, 256>>>((float*)d_out);
}

// round 14
// speedup vs baseline: 1.9497x; 1.0348x over previous
#include <cuda_runtime.h>
#include <cuda_fp16.h>
#include <cstdint>

typedef unsigned long long u64;

#define NTOK 8192
#define GCTAS 296
#define NUNITS 8192                      // 64 qtiles * 128 chunks

// ---- attn smem layout (bytes) ----
#define A_OFF    0                       // 128 rows x 128B phi (pitch 144)
#define B_OFF0   18432
#define B_OFF1   36864                   // psi tiles, 128 rows x 128B (pitch 144)
#define VT_OFF(p) (55296 + (p) * 1152)   // 8 rows x 128B (pitch 144)
#define P_OFF    57600                   // 8 warps x (32 rows x 80B) = 20480
#define RED_OFF  78080                   // 128 x 8 floats
#define SMEM_TOTAL 82176                 // x2 CTAs <= 228KB carveout

// ---- prep_gemm smem layout ----
#define PG_A   0
#define PG_B   18432
#define PG_T   36864                     // psi: 256 rows x 144B = 36864
#define PG_P   36864                     // V: 8 warps x 2560
#define PG_ST  57344                     // 8 x 144
#define PG_RED 58496                     // 128 x 8 floats
#define SMEM_PREP 73728

// ---------------- device scratch ----------------
__device__ __align__(16) __half g_a [NTOK * 64];    // phi_i (real, K=64)
__device__ __align__(16) __half g_b [NTOK * 128];   // rows 2j: Re(psi_j), 2j+1: Im(psi_j)
__device__ __align__(16) __half g_vt[8 * NTOK];     // rows 0-5: <Z_q>, row6: ones, row7: 0
__device__ __align__(16) __half g_bm[128 * 64];     // M = Pq^H Pk
__device__ __align__(16) __half g_wv[128 * 64];     // Pv
__device__ float g_part[(size_t)64 * 8 * 128 * 8];  // [qtile][slot(8)][tok][8]

// ---------------- PTX helpers ----------------
__device__ __forceinline__ uint32_t smem_u32(const void* p) {
    uint32_t a;
    asm("{ .reg .u64 t; cvta.to.shared.u64 t, %1; cvt.u32.u64 %0, t; }" : "=r"(a) : "l"(p));
    return a;
}
__device__ __forceinline__ void cp16(uint32_t s, const void* g) {
    asm volatile("cp.async.cg.shared.global [%0], [%1], 16;" :: "r"(s), "l"(g));
}
__device__ __forceinline__ void cp_commit() { asm volatile("cp.async.commit_group;"); }

__device__ __forceinline__ void ldsm_x4(uint32_t& r0, uint32_t& r1, uint32_t& r2, uint32_t& r3, uint32_t a) {
    asm volatile("ldmatrix.sync.aligned.m8n8.x4.shared.b16 {%0,%1,%2,%3}, [%4];"
                 : "=r"(r0), "=r"(r1), "=r"(r2), "=r"(r3) : "r"(a));
}
__device__ __forceinline__ void ldsm_x2(uint32_t& r0, uint32_t& r1, uint32_t a) {
    asm volatile("ldmatrix.sync.aligned.m8n8.x2.shared.b16 {%0,%1}, [%2];"
                 : "=r"(r0), "=r"(r1) : "r"(a));
}
__device__ __forceinline__ void mma16816(float* c, const uint32_t* a, const uint32_t* b) {
    asm volatile("mma.sync.aligned.m16n8k16.row.col.f32.f16.f16.f32 "
                 "{%0,%1,%2,%3}, {%4,%5,%6,%7}, {%8,%9}, {%0,%1,%2,%3};"
                 : "+f"(c[0]), "+f"(c[1]), "+f"(c[2]), "+f"(c[3])
                 : "r"(a[0]), "r"(a[1]), "r"(a[2]), "r"(a[3]), "r"(b[0]), "r"(b[1]));
}
__device__ __forceinline__ void sts16(uint32_t a, float v) {
    unsigned short u = __half_as_ushort(__float2half_rn(v));
    asm volatile("st.shared.b16 [%0], %1;" :: "r"(a), "h"(u));
}
// store lo/hi halves of a half2 to two smem addresses
__device__ __forceinline__ void sts16_pair(uint32_t a_lo, uint32_t a_hi, uint32_t h2) {
    unsigned short lo, hi;
    asm("mov.b32 {%0,%1}, %2;" : "=h"(lo), "=h"(hi) : "r"(h2));
    asm volatile("st.shared.b16 [%0], %1;" :: "r"(a_lo), "h"(lo));
    asm volatile("st.shared.b16 [%0], %1;" :: "r"(a_hi), "h"(hi));
}

// ---------------- quantum gates (warp-distributed 64-amp state) ----------------
__device__ __forceinline__ void ry_sc(float s, float c, int q, int lane,
        float& a0x, float& a0y, float& a1x, float& a1y)
{
    if (q == 5) {
        float n0x = c*a0x - s*a1x, n0y = c*a0y - s*a1y;
        float n1x = s*a0x + c*a1x, n1y = s*a0y + c*a1y;
        a0x = n0x; a0y = n0y; a1x = n1x; a1y = n1y;
    } else {
        int sh = 4 - q, m = 1 << sh;
        float o0x = __shfl_xor_sync(0xffffffffu, a0x, m);
        float o0y = __shfl_xor_sync(0xffffffffu, a0y, m);
        float o1x = __shfl_xor_sync(0xffffffffu, a1x, m);
        float o1y = __shfl_xor_sync(0xffffffffu, a1y, m);
        float sg = ((lane >> sh) & 1) ? s : -s;
        a0x = c*a0x + sg*o0x; a0y = c*a0y + sg*o0y;
        a1x = c*a1x + sg*o1x; a1y = c*a1y + sg*o1y;
    }
}

__device__ __forceinline__ void rz_sc(float s, float c, int q, int lane,
        float& a0x, float& a0y, float& a1x, float& a1y)
{
    if (q == 5) {
        float n0x = a0x*c + a0y*s, n0y = a0y*c - a0x*s;
        float n1x = a1x*c - a1y*s, n1y = a1y*c + a1x*s;
        a0x = n0x; a0y = n0y; a1x = n1x; a1y = n1y;
    } else {
        float t = ((lane >> (4 - q)) & 1) ? s : -s;
        float n0x = a0x*c - a0y*t, n0y = a0y*c + a0x*t;
        float n1x = a1x*c - a1y*t, n1y = a1y*c + a1x*t;
        a0x = n0x; a0y = n0y; a1x = n1x; a1y = n1y;
    }
}

__device__ __forceinline__ void cnot_ll(int csh, int tmask, int lane,
        float& a0x, float& a0y, float& a1x, float& a1y)
{
    float o0x = __shfl_xor_sync(0xffffffffu, a0x, tmask);
    float o0y = __shfl_xor_sync(0xffffffffu, a0y, tmask);
    float o1x = __shfl_xor_sync(0xffffffffu, a1x, tmask);
    float o1y = __shfl_xor_sync(0xffffffffu, a1y, tmask);
    if ((lane >> csh) & 1) { a0x = o0x; a0y = o0y; a1x = o1x; a1y = o1y; }
}

__device__ __forceinline__ void pqc_fwd(const float2* trig, int lane,
        float& a0x, float& a0y, float& a1x, float& a1y)
{
    #pragma unroll
    for (int l = 0; l < 2; l++) {
        #pragma unroll
        for (int q = 0; q < 6; q++) {
            float2 ty = trig[(l * 6 + q) * 2 + 0];
            ry_sc(ty.x, ty.y, q, lane, a0x, a0y, a1x, a1y);
            float2 tz = trig[(l * 6 + q) * 2 + 1];
            rz_sc(tz.x, tz.y, q, lane, a0x, a0y, a1x, a1y);
        }
        cnot_ll(4, 8, lane, a0x, a0y, a1x, a1y);
        cnot_ll(3, 4, lane, a0x, a0y, a1x, a1y);
        cnot_ll(2, 2, lane, a0x, a0y, a1x, a1y);
        cnot_ll(1, 1, lane, a0x, a0y, a1x, a1y);
        if (lane & 1) {
            float t;
            t = a0x; a0x = a1x; a1x = t;
            t = a0y; a0y = a1y; a1y = t;
        }
        a1x = __shfl_xor_sync(0xffffffffu, a1x, 16);
        a1y = __shfl_xor_sync(0xffffffffu, a1y, 16);
    }
}

__device__ __forceinline__ void pqc_inv(const float2* trig, int lane,
        float& a0x, float& a0y, float& a1x, float& a1y)
{
    #pragma unroll
    for (int l = 1; l >= 0; l--) {
        a1x = __shfl_xor_sync(0xffffffffu, a1x, 16);
        a1y = __shfl_xor_sync(0xffffffffu, a1y, 16);
        if (lane & 1) {
            float t;
            t = a0x; a0x = a1x; a1x = t;
            t = a0y; a0y = a1y; a1y = t;
        }
        cnot_ll(1, 1, lane, a0x, a0y, a1x, a1y);
        cnot_ll(2, 2, lane, a0x, a0y, a1x, a1y);
        cnot_ll(3, 4, lane, a0x, a0y, a1x, a1y);
        cnot_ll(4, 8, lane, a0x, a0y, a1x, a1y);
        #pragma unroll
        for (int q = 0; q < 6; q++) {
            float2 tz = trig[(l * 6 + q) * 2 + 1];
            rz_sc(-tz.x, tz.y, q, lane, a0x, a0y, a1x, a1y);
            float2 ty = trig[(l * 6 + q) * 2 + 0];
            ry_sc(-ty.x, ty.y, q, lane, a0x, a0y, a1x, a1y);
        }
    }
}

// ---------------- basis: materialize M = Pq^H Pk and Pv as fp16 B-matrices ----------------
__global__ void basis_kernel(const float* __restrict__ pq,
                             const float* __restrict__ pk,
                             const float* __restrict__ pv)
{
    __shared__ float2 strig[72];
    int tid = threadIdx.x;
    if (tid < 72) {
        int set = tid / 24, r = tid % 24;
        const float* p = (set == 0) ? pq : (set == 1) ? pk : pv;
        float s, c;
        sincosf(0.5f * p[r], &s, &c);
        strig[tid] = make_float2(s, c);
    }
    __syncthreads();

    int gw   = blockIdx.x * 8 + (tid >> 5);   // 0..127
    int lane = tid & 31;
    int d    = gw & 63;

    float a0x = (2 * lane == d) ? 1.f : 0.f, a0y = 0.f;
    float a1x = (2 * lane + 1 == d) ? 1.f : 0.f, a1y = 0.f;

    if (gw < 64) {
        pqc_fwd(strig + 24, lane, a0x, a0y, a1x, a1y);   // K-PQC
        pqc_inv(strig + 0,  lane, a0x, a0y, a1x, a1y);   // inverse Q-PQC
        g_bm[(4 * lane + 0) * 64 + d] = __float2half_rn(a0x);
        g_bm[(4 * lane + 1) * 64 + d] = __float2half_rn(a0y);
        g_bm[(4 * lane + 2) * 64 + d] = __float2half_rn(a1x);
        g_bm[(4 * lane + 3) * 64 + d] = __float2half_rn(a1y);
    } else {
        pqc_fwd(strig + 48, lane, a0x, a0y, a1x, a1y);   // V-PQC
        g_wv[(4 * lane + 0) * 64 + d] = __float2half_rn(a0x);
        g_wv[(4 * lane + 1) * 64 + d] = __float2half_rn(a0y);
        g_wv[(4 * lane + 2) * 64 + d] = __float2half_rn(a1x);
        g_wv[(4 * lane + 3) * 64 + d] = __float2half_rn(a1y);
    }
}

// ---------------- phi: tensor-product embedding state ----------------
__global__ void phi_kernel(const float* __restrict__ x)
{
    __shared__ __half buf[256 * 72];
    int tl = threadIdx.x;
    int tok = blockIdx.x * 256 + tl;

    float f[6][2];
    #pragma unroll
    for (int q = 0; q < 6; q++) {
        float s, c;
        __sincosf(0.5f * x[tok * 6 + q], &s, &c);
        f[q][0] = c; f[q][1] = s;
    }
    float t01[4], t23[4], t45[4];
    #pragma unroll
    for (int b = 0; b < 4; b++) {
        t01[b] = f[0][b >> 1] * f[1][b & 1];
        t23[b] = f[2][b >> 1] * f[3][b & 1];
        t45[b] = f[4][b >> 1] * f[5][b & 1];
    }
    #pragma unroll
    for (int d = 0; d < 64; d++)
        buf[tl * 72 + d] = __float2half_rn(t01[d >> 4] * t23[(d >> 2) & 3] * t45[d & 3]);
    __syncthreads();

    uint4* dst = (uint4*)(g_a + (size_t)(blockIdx.x * 256 + tl) * 64);
    #pragma unroll
    for (int k = 0; k < 8; k++)
        dst[k] = *(uint4*)(buf + tl * 72 + k * 8);
}

// ---------------- prep GEMM: psi = M phi  /  V from |Pv phi|^2 ----------------
extern __shared__ char smx[];

__global__ void __launch_bounds__(256) prep_gemm_kernel()
{
    char* sm = smx;
    uint32_t smb = smem_u32(sm);
    int tid  = threadIdx.x;
    int wid  = tid >> 5, lane = tid & 31;
    int wrow = wid & 3, wcol = wid >> 2;
    int mwarp = wrow * 32;
    int qbase = blockIdx.x * 128;
    const __half* gB = blockIdx.y ? g_wv : g_bm;

    #pragma unroll
    for (int e = 0; e < 4; e++) {
        int i = e * 256 + tid, row = i >> 3, ch = i & 7;
        cp16(smb + PG_A + row * 144 + ch * 16, g_a + (size_t)(qbase + row) * 64 + ch * 8);
    }
    #pragma unroll
    for (int e = 0; e < 4; e++) {
        int i = e * 256 + tid, row = i >> 3, ch = i & 7;
        cp16(smb + PG_B + row * 144 + ch * 16, gB + (size_t)row * 64 + ch * 8);
    }
    cp_commit();
    if (blockIdx.y == 1) {
        for (int i = tid; i < 512; i += 256) {
            int q = i >> 6, a = i & 63;
            float sg = (q < 6) ? (((a >> (5 - q)) & 1) ? -1.f : 1.f) : 0.f;
            *(__half*)(sm + PG_ST + q * 144 + a * 2) = __float2half_rn(sg);
        }
    }
    asm volatile("cp.async.wait_group 0;" ::: "memory");
    __syncthreads();

    uint32_t afr[2][4][4];
    {
        int rowa = mwarp + (lane & 15), offa = (lane >> 4) * 16;
        #pragma unroll
        for (int rt = 0; rt < 2; rt++)
            #pragma unroll
            for (int kt = 0; kt < 4; kt++)
                ldsm_x4(afr[rt][kt][0], afr[rt][kt][1], afr[rt][kt][2], afr[rt][kt][3],
                        smb + PG_A + (rowa + rt * 16) * 144 + kt * 32 + offa);
    }

    int brow_l = wcol * 64 + (lane >> 4) * 8 + (lane & 7);
    int boffk  = ((lane >> 3) & 1) * 16;
    int l4 = lane & 15;

    float acc[2][8][4];
    #pragma unroll
    for (int rt = 0; rt < 2; rt++)
        #pragma unroll
        for (int ct = 0; ct < 8; ct++)
            #pragma unroll
            for (int e = 0; e < 4; e++) acc[rt][ct][e] = 0.f;

    #pragma unroll
    for (int kt = 0; kt < 4; kt++) {
        uint32_t bfr[8][2];
        #pragma unroll
        for (int cp2 = 0; cp2 < 4; cp2++) {
            uint32_t r0, r1, r2, r3;
            ldsm_x4(r0, r1, r2, r3,
                    smb + PG_B + (brow_l + cp2 * 16) * 144 + kt * 32 + boffk);
            bfr[2*cp2][0] = r0; bfr[2*cp2][1] = r1;
            bfr[2*cp2+1][0] = r2; bfr[2*cp2+1][1] = r3;
        }
        #pragma unroll
        for (int ct = 0; ct < 8; ct++)
            #pragma unroll
            for (int rt = 0; rt < 2; rt++)
                mma16816(acc[rt][ct], afr[rt][kt], bfr[ct]);
    }

    if (blockIdx.y == 0) {
        #pragma unroll
        for (int rt = 0; rt < 2; rt++)
            #pragma unroll
            for (int ct = 0; ct < 8; ct++) {
                int r0 = mwarp + rt * 16 + (lane >> 2);
                int d  = wcol * 32 + ct * 4 + (lane & 3);
                sts16(smb + PG_T + (2 * r0) * 144 + d * 2,       acc[rt][ct][0]);
                sts16(smb + PG_T + (2 * r0 + 1) * 144 + d * 2,   acc[rt][ct][1]);
                sts16(smb + PG_T + (2 * (r0 + 8)) * 144 + d * 2,     acc[rt][ct][2]);
                sts16(smb + PG_T + (2 * (r0 + 8) + 1) * 144 + d * 2, acc[rt][ct][3]);
            }
        __syncthreads();
        uint4* dst = (uint4*)(g_b + ((size_t)qbase * 2 + tid) * 64);
        #pragma unroll
        for (int k = 0; k < 8; k++)
            dst[k] = *(uint4*)(sm + PG_T + tid * 144 + k * 16);
    } else {
        uint32_t pbase = smb + PG_P + wid * 2560;
        #pragma unroll
        for (int rt = 0; rt < 2; rt++)
            #pragma unroll
            for (int ct = 0; ct < 8; ct++) {
                int rl = rt * 16 + (lane >> 2);
                int dl = ct * 4 + (lane & 3);
                float p0 = fmaf(acc[rt][ct][0], acc[rt][ct][0], acc[rt][ct][1] * acc[rt][ct][1]);
                float p1 = fmaf(acc[rt][ct][2], acc[rt][ct][2], acc[rt][ct][3] * acc[rt][ct][3]);
                sts16(pbase + rl * 80 + dl * 2, p0);
                sts16(pbase + (rl + 8) * 80 + dl * 2, p1);
            }
        __syncwarp();
        float O[2][4];
        #pragma unroll
        for (int rt = 0; rt < 2; rt++)
            #pragma unroll
            for (int e = 0; e < 4; e++) O[rt][e] = 0.f;
        #pragma unroll
        for (int kt2 = 0; kt2 < 2; kt2++) {
            uint32_t bb[2];
            ldsm_x2(bb[0], bb[1],
                    smb + PG_ST + (l4 & 7) * 144 + wcol * 64 + kt2 * 32 + (l4 >> 3) * 16);
            #pragma unroll
            for (int rt2 = 0; rt2 < 2; rt2++) {
                uint32_t a4[4];
                ldsm_x4(a4[0], a4[1], a4[2], a4[3],
                        pbase + ((lane & 15) + rt2 * 16) * 80 + kt2 * 32 + (lane >> 4) * 16);
                mma16816(O[rt2], a4, bb);
            }
        }
        float2* red = (float2*)(sm + PG_RED);
        __syncthreads();
        int r0 = mwarp + (lane >> 2), cc = lane & 3;
        if (wcol == 0) {
            #pragma unroll
            for (int rt = 0; rt < 2; rt++) {
                red[(r0 + rt * 16) * 4 + cc]     = make_float2(O[rt][0], O[rt][1]);
                red[(r0 + rt * 16 + 8) * 4 + cc] = make_float2(O[rt][2], O[rt][3]);
            }
        }
        __syncthreads();
        if (wcol == 1) {
            #pragma unroll
            for (int rt = 0; rt < 2; rt++) {
                float2 v0 = red[(r0 + rt * 16) * 4 + cc];
                v0.x += O[rt][0]; v0.y += O[rt][1];
                red[(r0 + rt * 16) * 4 + cc] = v0;
                float2 v1 = red[(r0 + rt * 16 + 8) * 4 + cc];
                v1.x += O[rt][2]; v1.y += O[rt][3];
                red[(r0 + rt * 16 + 8) * 4 + cc] = v1;
            }
        }
        __syncthreads();
        if (tid < 128) {
            int token = qbase + tid;
            const float* rp = (const float*)(sm + PG_RED) + tid * 8;
            #pragma unroll
            for (int q = 0; q < 6; q++)
                g_vt[q * NTOK + token] = __float2half_rn(rp[q]);
            g_vt[6 * NTOK + token] = __float2half_rn(1.f);
            g_vt[7 * NTOK + token] = __float2half_rn(0.f);
        }
    }
}

// ---------------- fused attention ----------------
__device__ __forceinline__ void issue_chunk(uint32_t smb, uint32_t boff, uint32_t vtoff,
                                            int kb, int tid)
{
    #pragma unroll
    for (int it = 0; it < 5; it++) {
        int i = it * 256 + tid;
        if (i < 1024) {
            int row = i >> 3, ch = i & 7;
            cp16(smb + boff + row * 144 + ch * 16,
                 g_b + (size_t)(kb * 2 + row) * 64 + ch * 8);
        } else if (i < 1088) {
            int j = i - 1024, row = j >> 3, ch = j & 7;
            cp16(smb + vtoff + row * 144 + ch * 16,
                 g_vt + (size_t)row * NTOK + kb + ch * 8);
        }
    }
    cp_commit();
}

__device__ __forceinline__ void flush_O(char* sm, float O[2][4], int b, int q,
                                        int mwarp, int wcol, int lane, int tid)
{
    float2* red = (float2*)(sm + RED_OFF);
    __syncthreads();
    int r0 = mwarp + (lane >> 2);
    int cc = lane & 3;
    if (wcol == 0) {
        #pragma unroll
        for (int rt = 0; rt < 2; rt++) {
            red[(r0 + rt * 16) * 4 + cc]     = make_float2(O[rt][0], O[rt][1]);
            red[(r0 + rt * 16 + 8) * 4 + cc] = make_float2(O[rt][2], O[rt][3]);
        }
    }
    __syncthreads();
    if (wcol == 1) {
        #pragma unroll
        for (int rt = 0; rt < 2; rt++) {
            float2 v0 = red[(r0 + rt * 16) * 4 + cc];
            v0.x += O[rt][0]; v0.y += O[rt][1];
            red[(r0 + rt * 16) * 4 + cc] = v0;
            float2 v1 = red[(r0 + rt * 16 + 8) * 4 + cc];
            v1.x += O[rt][2]; v1.y += O[rt][3];
            red[(r0 + rt * 16 + 8) * 4 + cc] = v1;
        }
    }
    __syncthreads();
    if (tid < 128) {
        int slot = b - (int)(((long long)(q * 128 + 1) * GCTAS - 1) / NUNITS);
        const float4* src = (const float4*)((const float*)(sm + RED_OFF) + tid * 8);
        float4* dst = (float4*)(g_part + ((size_t)(q * 8 + slot) * 128 + tid) * 8);
        dst[0] = src[0]; dst[1] = src[1];
    }
}

__global__ void __launch_bounds__(256, 2) attn_kernel()
{
    char* sm = smx;
    uint32_t smb = smem_u32(sm);
    int tid  = threadIdx.x;
    int wid  = tid >> 5, lane = tid & 31;
    int wrow = wid & 3, wcol = wid >> 2;
    int mwarp = wrow * 32;
    int b = blockIdx.x;
    int u0 = (int)(((long long)NUNITS * b) / GCTAS);
    int u1 = (int)(((long long)NUNITS * (b + 1)) / GCTAS);

    uint32_t pbase = smb + P_OFF + wid * 2560;

    // half2 exp poly constants: e^{0.5+u}, Taylor deg5 in u = l - 0.5
    const __half2 C5 = __floats2half2_rn(0.013739344f, 0.013739344f);
    const __half2 C4 = __floats2half2_rn(0.068696720f, 0.068696720f);
    const __half2 C3 = __floats2half2_rn(0.274786878f, 0.274786878f);
    const __half2 C2 = __floats2half2_rn(0.824360635f, 0.824360635f);
    const __half2 C1 = __floats2half2_rn(1.648721271f, 1.648721271f);
    const __half2 C0 = C1;

    {
        int p0 = u0 & 1;
        issue_chunk(smb, p0 ? B_OFF1 : B_OFF0, VT_OFF(p0), 64 * (u0 & 127), tid);
    }

    uint32_t afr[2][4][4];
    float O[2][4];
    int qcur = -1;
    int brow_l = wcol * 64 + (lane >> 4) * 8 + (lane & 7);
    int boffk  = ((lane >> 3) & 1) * 16;
    int l4 = lane & 15;

    for (int u = u0; u < u1; u++) {
        int q = u >> 7, p = u & 1;
        bool newq = (q != qcur);
        bool pref = (u + 1 < u1);

        if (newq) {
            if (qcur >= 0) flush_O(sm, O, b, qcur, mwarp, wcol, lane, tid);
            #pragma unroll
            for (int e = 0; e < 4; e++) {
                int i = e * 256 + tid, row = i >> 3, ch = i & 7;
                cp16(smb + A_OFF + row * 144 + ch * 16,
                     g_a + (size_t)(q * 128 + row) * 64 + ch * 8);
            }
            cp_commit();
            qcur = q;
        }
        if (pref)
            issue_chunk(smb, ((u + 1) & 1) ? B_OFF1 : B_OFF0, VT_OFF((u + 1) & 1),
                        64 * ((u + 1) & 127), tid);
        if (newq) {
            if (pref) asm volatile("cp.async.wait_group 1;" ::: "memory");
            else      asm volatile("cp.async.wait_group 0;" ::: "memory");
            __syncthreads();
            int rowa = mwarp + (lane & 15), offa = (lane >> 4) * 16;
            #pragma unroll
            for (int rt = 0; rt < 2; rt++)
                #pragma unroll
                for (int kt = 0; kt < 4; kt++)
                    ldsm_x4(afr[rt][kt][0], afr[rt][kt][1], afr[rt][kt][2], afr[rt][kt][3],
                            smb + A_OFF + (rowa + rt * 16) * 144 + kt * 32 + offa);
            #pragma unroll
            for (int rt = 0; rt < 2; rt++)
                #pragma unroll
                for (int e = 0; e < 4; e++) O[rt][e] = 0.f;
        }

        uint32_t boff = p ? B_OFF1 : B_OFF0;
        #pragma unroll
        for (int h = 0; h < 2; h++) {
            float acc[2][4][4];
            #pragma unroll
            for (int rt = 0; rt < 2; rt++)
                #pragma unroll
                for (int ct = 0; ct < 4; ct++)
                    #pragma unroll
                    for (int e = 0; e < 4; e++) acc[rt][ct][e] = 0.f;

            #pragma unroll
            for (int kt = 0; kt < 4; kt++) {
                uint32_t bfr[4][2];
                #pragma unroll
                for (int cp2 = 0; cp2 < 2; cp2++) {
                    uint32_t r0, r1, r2, r3;
                    ldsm_x4(r0, r1, r2, r3,
                            smb + boff + (brow_l + (2 * h + cp2) * 16) * 144 + kt * 32 + boffk);
                    bfr[2*cp2][0] = r0; bfr[2*cp2][1] = r1;
                    bfr[2*cp2+1][0] = r2; bfr[2*cp2+1][1] = r3;
                }
                #pragma unroll
                for (int ct = 0; ct < 4; ct++)
                    #pragma unroll
                    for (int rt = 0; rt < 2; rt++)
                        mma16816(acc[rt][ct], afr[rt][kt], bfr[ct]);
            }

            // convert acc -> P via half2 poly exp (no MUFU)
            #pragma unroll
            for (int ct = 0; ct < 4; ct++) {
                int key = h * 16 + ct * 4 + (lane & 3);
                #pragma unroll
                for (int rt = 0; rt < 2; rt++) {
                    int r = rt * 16 + (lane >> 2);
                    // u = logit - 0.5, folded into the FMA chain
                    float u0f = fmaf(acc[rt][ct][1], acc[rt][ct][1],
                                     fmaf(acc[rt][ct][0], acc[rt][ct][0], -0.5f));
                    float u1f = fmaf(acc[rt][ct][3], acc[rt][ct][3],
                                     fmaf(acc[rt][ct][2], acc[rt][ct][2], -0.5f));
                    uint32_t upk;
                    asm("cvt.rn.f16x2.f32 %0, %1, %2;" : "=r"(upk) : "f"(u1f), "f"(u0f)); // hi=u1, lo=u0
                    __half2 v = *reinterpret_cast<__half2*>(&upk);
                    __half2 pp = __hfma2(C5, v, C4);
                    pp = __hfma2(pp, v, C3);
                    pp = __hfma2(pp, v, C2);
                    pp = __hfma2(pp, v, C1);
                    pp = __hfma2(pp, v, C0);
                    sts16_pair(pbase + r * 80 + key * 2,
                               pbase + (r + 8) * 80 + key * 2,
                               *reinterpret_cast<uint32_t*>(&pp));
                }
            }
        }
        __syncwarp();

        uint32_t vtb = smb + VT_OFF(p);
        #pragma unroll
        for (int kt2 = 0; kt2 < 2; kt2++) {
            uint32_t bb[2];
            ldsm_x2(bb[0], bb[1],
                    vtb + (l4 & 7) * 144 + wcol * 64 + kt2 * 32 + (l4 >> 3) * 16);
            #pragma unroll
            for (int rt2 = 0; rt2 < 2; rt2++) {
                uint32_t a4[4];
                ldsm_x4(a4[0], a4[1], a4[2], a4[3],
                        pbase + ((lane & 15) + rt2 * 16) * 80 + kt2 * 32 + (lane >> 4) * 16);
                mma16816(O[rt2], a4, bb);
            }
        }

        if (pref) {
            asm volatile("cp.async.wait_group 0;" ::: "memory");
            __syncthreads();
        }
    }
    flush_O(sm, O, b, qcur, mwarp, wcol, lane, tid);
}

// one thread per (token, component): 8x parallelism vs before
__global__ void finalize_kernel(float* __restrict__ out)
{
    int idx = blockIdx.x * blockDim.x + threadIdx.x;   // 65536
    int t = idx >> 3, c = idx & 7;
    int q = t >> 7, r = t & 127;
    int ca = (int)(((long long)(q * 128 + 1)   * GCTAS - 1) / NUNITS);
    int cb = (int)(((long long)(q * 128 + 128) * GCTAS - 1) / NUNITS);
    float acc = 0.f;
    for (int s = 0; s <= cb - ca; s++)
        acc += g_part[((size_t)(q * 8 + s) * 128 + r) * 8 + c];
    float den = __shfl_sync(0xffffffffu, acc, 6, 8);   // component 6 within this token's 8-lane group
    if (c < 6)
        out[t * 6 + c] = acc * (1.0f / den);
}

extern "C" void kernel_launch(void* const* d_in, const int* in_sizes, int n_in,
                              void* d_out, int out_size)
{
    const float* x  = (const float*)d_in[0];
    const float* pq = (const float*)d_in[1];
    const float* pk = (const float*)d_in[2];
    const float* pv = (const float*)d_in[3];

    basis_kernel<<<16, 256>>>(pq, pk, pv);
    phi_kernel<<<NTOK / 256, 256>>>(x);

    cudaFuncSetAttribute(prep_gemm_kernel, cudaFuncAttributeMaxDynamicSharedMemorySize, SMEM_PREP);
    prep_gemm_kernel<<<dim3(64, 2), 256, SMEM_PREP>>>();

    cudaFuncSetAttribute(attn_kernel, cudaFuncAttributeMaxDynamicSharedMemorySize, SMEM_TOTAL);
    attn_kernel<<<GCTAS, 256, SMEM_TOTAL>>>();

    finalize_kernel<<<NTOK * 8 / 256, 256>>>((float*)d_out);
}